// round 1
// baseline (speedup 1.0000x reference)
#include <cuda_runtime.h>
#include <math.h>

// Problem shape (fixed by the dataset)
#define Bsz 4
#define Ssz 2048
#define Hsz 2048
#define NH  16
#define HD  128
#define Msz (Bsz*Ssz)   // 8192 tokens

// Scratch (no cudaMalloc allowed): Q,K,V in head-split layout [B,nh,S,hd], attn out [B,S,H]
__device__ float g_q[(size_t)Bsz*NH*Ssz*HD];
__device__ float g_k[(size_t)Bsz*NH*Ssz*HD];
__device__ float g_v[(size_t)Bsz*NH*Ssz*HD];
__device__ float g_ao[(size_t)Msz*Hsz];

// ---------------------------------------------------------------------------
// Tiled fp32 GEMM with bias: out = A[M,K] @ W[K,N] + bias[N]
// BM=BN=128, BK=16, 256 threads, 8x8 per thread.
// HEADSPLIT epilogue writes [B, nh, S, hd] instead of [M, N].
// ---------------------------------------------------------------------------
#define BM 128
#define BN 128
#define BK 16

template<bool HEADSPLIT>
__global__ void __launch_bounds__(256) sgemm_bias_kernel(
    const float* __restrict__ A, const float* __restrict__ W,
    const float* __restrict__ bias, float* __restrict__ out)
{
    __shared__ float As[BK][BM];   // transposed A tile: As[k][m]
    __shared__ float Bs[BK][BN];

    const int tid = threadIdx.x;
    const int bm = blockIdx.y * BM;
    const int bn = blockIdx.x * BN;
    const int tx = tid & 15;       // 0..15 -> 8 output cols each
    const int ty = tid >> 4;       // 0..15 -> 8 output rows each

    // A-load mapping: 2 float4 per thread
    const int ar = tid >> 2;        // 0..63
    const int ac = (tid & 3) * 4;   // 0,4,8,12
    // B-load mapping: 2 float4 per thread
    const int br = tid >> 5;        // 0..7
    const int bc = (tid & 31) * 4;  // 0..124

    float acc[8][8];
    #pragma unroll
    for (int i = 0; i < 8; i++)
        #pragma unroll
        for (int j = 0; j < 8; j++) acc[i][j] = 0.f;

    for (int k0 = 0; k0 < Hsz; k0 += BK) {
        // A tile 128x16 -> transposed into As[k][m]
        #pragma unroll
        for (int rr = 0; rr < 2; rr++) {
            int row = ar + rr * 64;
            float4 v = *(const float4*)(A + (size_t)(bm + row) * Hsz + k0 + ac);
            As[ac + 0][row] = v.x;
            As[ac + 1][row] = v.y;
            As[ac + 2][row] = v.z;
            As[ac + 3][row] = v.w;
        }
        // B tile 16x128
        #pragma unroll
        for (int rr = 0; rr < 2; rr++) {
            int row = br + rr * 8;
            float4 v = *(const float4*)(W + (size_t)(k0 + row) * Hsz + bn + bc);
            *(float4*)&Bs[row][bc] = v;
        }
        __syncthreads();

        #pragma unroll
        for (int k = 0; k < BK; k++) {
            float a[8], b[8];
            *(float4*)&a[0] = *(const float4*)&As[k][ty * 8];
            *(float4*)&a[4] = *(const float4*)&As[k][ty * 8 + 4];
            *(float4*)&b[0] = *(const float4*)&Bs[k][tx * 8];
            *(float4*)&b[4] = *(const float4*)&Bs[k][tx * 8 + 4];
            #pragma unroll
            for (int i = 0; i < 8; i++)
                #pragma unroll
                for (int j = 0; j < 8; j++)
                    acc[i][j] += a[i] * b[j];
        }
        __syncthreads();
    }

    #pragma unroll
    for (int i = 0; i < 8; i++) {
        int m = bm + ty * 8 + i;
        int b = m / Ssz, s = m % Ssz;
        #pragma unroll
        for (int j = 0; j < 8; j++) {
            int n = bn + tx * 8 + j;
            float v = acc[i][j] + bias[n];
            if (HEADSPLIT) {
                int h = n >> 7;        // n / HD
                int d = n & (HD - 1);  // n % HD
                out[(((size_t)(b * NH + h)) * Ssz + s) * HD + d] = v;
            } else {
                out[(size_t)m * Hsz + n] = v;
            }
        }
    }
}

// ---------------------------------------------------------------------------
// Flash attention (fp32, online softmax). One warp per query row, 8 rows/block.
// K/V streamed in 32-key tiles through smem; pitch-33 float4 layout keeps both
// the per-lane dot loop and the P@V loop LDS-conflict-free.
// Q,K,V layout: [B*nh, S, hd].  Output written back to [B, S, H].
// ---------------------------------------------------------------------------
#define TK 32
#define PITCH4 33   // float4 pitch per key row (132 floats)

__global__ void __launch_bounds__(256) flash_attn_kernel(
    const float* __restrict__ Q, const float* __restrict__ K,
    const float* __restrict__ V, float* __restrict__ out)
{
    __shared__ float4 Ks[TK * PITCH4];
    __shared__ float4 Vs[TK * PITCH4];
    __shared__ float4 qs[8][HD / 4];

    const int tid  = threadIdx.x;
    const int warp = tid >> 5;
    const int lane = tid & 31;
    const int bh   = blockIdx.y;                // b*NH + h
    const int qrow = blockIdx.x * 8 + warp;

    const float* Qh = Q + ((size_t)bh * Ssz + qrow) * HD;
    const float* Kh = K + (size_t)bh * Ssz * HD;
    const float* Vh = V + (size_t)bh * Ssz * HD;

    // each warp stages its own q row (float4 per lane = 128 floats)
    qs[warp][lane] = *(const float4*)(Qh + lane * 4);
    __syncwarp();

    const float scale = 0.08838834764831843f;   // 1/sqrt(128)
    float  m_run = -1e30f, l_run = 0.f;
    float4 acc = make_float4(0.f, 0.f, 0.f, 0.f);

    for (int kt = 0; kt < Ssz; kt += TK) {
        __syncthreads();
        // stage 32 keys + 32 values: 8 warps x 4 passes, one 128-float row per warp-pass
        #pragma unroll
        for (int p = 0; p < 4; p++) {
            int row = warp + p * 8;
            Ks[row * PITCH4 + lane] = *(const float4*)(Kh + (size_t)(kt + row) * HD + lane * 4);
            Vs[row * PITCH4 + lane] = *(const float4*)(Vh + (size_t)(kt + row) * HD + lane * 4);
        }
        __syncthreads();

        // lane j computes the full 128-dim dot for key j of this tile
        float sc = 0.f;
        #pragma unroll
        for (int d4 = 0; d4 < HD / 4; d4++) {
            float4 kv = Ks[lane * PITCH4 + d4];
            float4 qv = qs[warp][d4];           // broadcast
            sc += kv.x * qv.x + kv.y * qv.y + kv.z * qv.z + kv.w * qv.w;
        }
        sc *= scale;

        // online softmax across the 32-key tile
        float mt = sc;
        #pragma unroll
        for (int off = 16; off > 0; off >>= 1)
            mt = fmaxf(mt, __shfl_xor_sync(0xffffffffu, mt, off));
        float m_new = fmaxf(m_run, mt);
        float corr  = __expf(m_run - m_new);
        float p     = __expf(sc - m_new);
        float lsum  = p;
        #pragma unroll
        for (int off = 16; off > 0; off >>= 1)
            lsum += __shfl_xor_sync(0xffffffffu, lsum, off);
        l_run = l_run * corr + lsum;
        m_run = m_new;
        acc.x *= corr; acc.y *= corr; acc.z *= corr; acc.w *= corr;

        // acc(1x128, lane owns 4 dims) += P(1x32) @ V(32x128)
        #pragma unroll
        for (int j = 0; j < TK; j++) {
            float  pj = __shfl_sync(0xffffffffu, p, j);
            float4 vv = Vs[j * PITCH4 + lane];
            acc.x += pj * vv.x; acc.y += pj * vv.y;
            acc.z += pj * vv.z; acc.w += pj * vv.w;
        }
    }

    float inv_l = 1.f / l_run;
    acc.x *= inv_l; acc.y *= inv_l; acc.z *= inv_l; acc.w *= inv_l;

    const int b = bh / NH, h = bh % NH;
    float* optr = out + ((size_t)(b * Ssz + qrow)) * Hsz + h * HD + lane * 4;
    *(float4*)optr = acc;
}

// ---------------------------------------------------------------------------
extern "C" void kernel_launch(void* const* d_in, const int* in_sizes, int n_in,
                              void* d_out, int out_size)
{
    const float* x  = (const float*)d_in[0];
    const float* Wq = (const float*)d_in[1];
    const float* bq = (const float*)d_in[2];
    const float* Wk = (const float*)d_in[3];
    const float* bk = (const float*)d_in[4];
    const float* Wv = (const float*)d_in[5];
    const float* bv = (const float*)d_in[6];
    const float* Wo = (const float*)d_in[7];
    const float* bo = (const float*)d_in[8];
    float* out = (float*)d_out;

    float *q, *k, *v, *ao;
    cudaGetSymbolAddress((void**)&q,  g_q);
    cudaGetSymbolAddress((void**)&k,  g_k);
    cudaGetSymbolAddress((void**)&v,  g_v);
    cudaGetSymbolAddress((void**)&ao, g_ao);

    dim3 gemm_grid(Hsz / BN, Msz / BM);   // (16, 64)
    dim3 attn_grid(Ssz / 8, Bsz * NH);    // (256, 64)

    sgemm_bias_kernel<true><<<gemm_grid, 256>>>(x, Wq, bq, q);
    sgemm_bias_kernel<true><<<gemm_grid, 256>>>(x, Wk, bk, k);
    sgemm_bias_kernel<true><<<gemm_grid, 256>>>(x, Wv, bv, v);
    flash_attn_kernel<<<attn_grid, 256>>>(q, k, v, ao);
    sgemm_bias_kernel<false><<<gemm_grid, 256>>>(ao, Wo, bo, out);
}

// round 4
// speedup vs baseline: 2.8239x; 2.8239x over previous
#include <cuda_runtime.h>
#include <cuda_bf16.h>
#include <math.h>

// Problem shape
#define Bsz 4
#define Ssz 2048
#define Hsz 2048
#define NH  16
#define HD  128
#define Msz (Bsz*Ssz)          // 8192
#define MK  ((size_t)Msz*Hsz)  // 16,777,216
#define WK  ((size_t)Hsz*Hsz)  // 4,194,304

// ---------------- scratch (__device__ globals; no cudaMalloc allowed) ------
__device__ __nv_bfloat16 g_xhi[MK], g_xlo[MK];
__device__ __nv_bfloat16 g_whi[4][WK], g_wlo[4][WK];   // W^T split, [N][K]
__device__ float g_q[MK], g_k[MK], g_v[MK];            // [B*nh][S][hd]
__device__ float g_ao[MK];                             // [B*S][H]
__device__ __nv_bfloat16 g_aohi[MK], g_aolo[MK];

// ---------------- PTX helpers ---------------------------------------------
__device__ __forceinline__ unsigned smem_u32(const void* p) {
    unsigned a;
    asm("{ .reg .u64 t; cvta.to.shared.u64 t, %1; cvt.u32.u64 %0, t; }"
        : "=r"(a) : "l"(p));
    return a;
}
__device__ __forceinline__ void ldsm_x4(unsigned& r0, unsigned& r1,
                                        unsigned& r2, unsigned& r3, unsigned a) {
    asm volatile("ldmatrix.sync.aligned.m8n8.x4.shared.b16 {%0,%1,%2,%3}, [%4];"
                 : "=r"(r0), "=r"(r1), "=r"(r2), "=r"(r3) : "r"(a));
}
__device__ __forceinline__ void mma16816(float* c, unsigned a0, unsigned a1,
                                         unsigned a2, unsigned a3,
                                         unsigned b0, unsigned b1) {
    asm volatile(
        "mma.sync.aligned.m16n8k16.row.col.f32.bf16.bf16.f32 "
        "{%0,%1,%2,%3}, {%4,%5,%6,%7}, {%8,%9}, {%0,%1,%2,%3};"
        : "+f"(c[0]), "+f"(c[1]), "+f"(c[2]), "+f"(c[3])
        : "r"(a0), "r"(a1), "r"(a2), "r"(a3), "r"(b0), "r"(b1));
}
__device__ __forceinline__ void cp16(unsigned dst, const void* src) {
    asm volatile("{ .reg .u64 g; cvta.to.global.u64 g, %1;\n\t"
                 "cp.async.cg.shared.global [%0], [g], 16; }"
                 :: "r"(dst), "l"(src) : "memory");
}
#define CP_COMMIT() asm volatile("cp.async.commit_group;" ::: "memory")
#define CP_WAIT1()  asm volatile("cp.async.wait_group 1;" ::: "memory")
#define CP_WAIT0()  asm volatile("cp.async.wait_group 0;" ::: "memory")

// packed f32x2
#define FMA2(d, a, b, c) \
    asm("fma.rn.f32x2 %0, %1, %2, %3;" : "=l"(d) : "l"(a), "l"(b), "l"(c))
#define MUL2(d, a, b) \
    asm("mul.rn.f32x2 %0, %1, %2;" : "=l"(d) : "l"(a), "l"(b))
__device__ __forceinline__ unsigned long long pk2(float x, float y) {
    unsigned long long r;
    asm("mov.b64 %0, {%1,%2};" : "=l"(r) : "f"(x), "f"(y));
    return r;
}
#define UNPK(lo, hi, v) asm("mov.b64 {%0,%1}, %2;" : "=f"(lo), "=f"(hi) : "l"(v))

// ---------------- conversion kernels --------------------------------------
__global__ void split_kernel(const float* __restrict__ in,
                             __nv_bfloat16* __restrict__ hi,
                             __nv_bfloat16* __restrict__ lo, size_t n) {
    for (size_t i = blockIdx.x * blockDim.x + threadIdx.x; i < n;
         i += (size_t)gridDim.x * blockDim.x) {
        float f = in[i];
        __nv_bfloat16 h = __float2bfloat16(f);
        hi[i] = h;
        lo[i] = __float2bfloat16(f - __bfloat162float(h));
    }
}

// W[K][N] -> Wt_hi/lo[N][K] (split bf16)
__global__ void tsplit_kernel(const float* __restrict__ W,
                              __nv_bfloat16* __restrict__ hi,
                              __nv_bfloat16* __restrict__ lo) {
    __shared__ float tile[32][33];
    int bx = blockIdx.x * 32, by = blockIdx.y * 32;
    int tx = threadIdx.x, ty = threadIdx.y;
    #pragma unroll
    for (int i = 0; i < 32; i += 8)
        tile[ty + i][tx] = W[(size_t)(by + ty + i) * Hsz + bx + tx];
    __syncthreads();
    #pragma unroll
    for (int i = 0; i < 32; i += 8) {
        int n = bx + ty + i, k = by + tx;
        float f = tile[tx][ty + i];
        __nv_bfloat16 h = __float2bfloat16(f);
        hi[(size_t)n * Hsz + k] = h;
        lo[(size_t)n * Hsz + k] = __float2bfloat16(f - __bfloat162float(h));
    }
}

// ---------------- mma.sync split-bf16 GEMM ---------------------------------
// C[M,N] = A@B^T + bias. A=[M,K] hi/lo bf16 K-major, B=[N,K] hi/lo K-major.
// Block 128x128, K-chunk 32. 8 warps in 2(m) x 4(n); warp tile 64x32.
// smem tiles: pitch 40 bf16 (5 quads, odd -> conflict-free LDSM).
// 3 passes: Ah*Bh + Ah*Bl + Al*Bh with fp32 accumulators.
#define TPITCH 80                  // bytes per smem row (40 bf16)
#define TILE_B (128*TPITCH)        // 10240 bytes per tile
#define BUF_B  (4*TILE_B)          // Ah,Al,Bh,Bl
#define GSMEM  (2*BUF_B)           // 81920 double-buffered

__device__ __forceinline__ void gemm_issue(const __nv_bfloat16* const* src,
                                           unsigned sb, int buf, int k0, int tid) {
    #pragma unroll
    for (int t = 0; t < 4; t++) {
        #pragma unroll
        for (int i = 0; i < 2; i++) {
            int s = tid + i * 256;         // 0..511
            int row = s >> 2, sq = s & 3;
            unsigned d = sb + buf * BUF_B + t * TILE_B + row * TPITCH + sq * 16;
            cp16(d, src[t] + (size_t)row * Hsz + k0 + sq * 8);
        }
    }
    CP_COMMIT();
}

template<bool HEADSPLIT>
__global__ void __launch_bounds__(256, 1) gemm_mma(
    const __nv_bfloat16* __restrict__ Ah, const __nv_bfloat16* __restrict__ Al,
    const __nv_bfloat16* __restrict__ Bh, const __nv_bfloat16* __restrict__ Bl,
    const float* __restrict__ bias, float* __restrict__ out)
{
    extern __shared__ char smc[];
    const unsigned sb = smem_u32(smc);
    const int tid = threadIdx.x, wid = tid >> 5, lane = tid & 31;
    const int wm = wid >> 2, wn = wid & 3;         // 2 x 4 warp grid
    const size_t bm = (size_t)blockIdx.y * 128, bn = (size_t)blockIdx.x * 128;

    const __nv_bfloat16* src[4] = { Ah + bm * Hsz, Al + bm * Hsz,
                                    Bh + bn * Hsz, Bl + bn * Hsz };

    float acc[4][4][4];
    #pragma unroll
    for (int mi = 0; mi < 4; mi++)
        #pragma unroll
        for (int ni = 0; ni < 4; ni++)
            #pragma unroll
            for (int r = 0; r < 4; r++) acc[mi][ni][r] = 0.f;

    // ldmatrix lane offset: row = (lane&15), col-quad = lane>>4
    const unsigned lm_off = (unsigned)((lane & 15) * TPITCH + (lane >> 4) * 16);

    gemm_issue(src, sb, 0, 0, tid);

    #pragma unroll 1
    for (int c = 0; c < 64; c++) {
        const int buf = c & 1;
        if (c < 63) { gemm_issue(src, sb, buf ^ 1, (c + 1) * 32, tid); CP_WAIT1(); }
        else        { CP_WAIT0(); }
        __syncthreads();

        const unsigned base = sb + buf * BUF_B;
        #pragma unroll
        for (int pass = 0; pass < 3; pass++) {
            const unsigned abase = base + (pass == 2 ? TILE_B : 0u)
                                 + (unsigned)(wm * 64 * TPITCH) + lm_off;
            const unsigned bbase = base + 2u * TILE_B + (pass == 1 ? TILE_B : 0u)
                                 + (unsigned)(wn * 32 * TPITCH) + lm_off;
            #pragma unroll
            for (int ks = 0; ks < 2; ks++) {
                unsigned a[4][4], bf[2][4];
                #pragma unroll
                for (int mi = 0; mi < 4; mi++)
                    ldsm_x4(a[mi][0], a[mi][1], a[mi][2], a[mi][3],
                            abase + mi * 16 * TPITCH + ks * 32);
                #pragma unroll
                for (int bi = 0; bi < 2; bi++)
                    ldsm_x4(bf[bi][0], bf[bi][1], bf[bi][2], bf[bi][3],
                            bbase + bi * 16 * TPITCH + ks * 32);
                #pragma unroll
                for (int mi = 0; mi < 4; mi++)
                    #pragma unroll
                    for (int ni = 0; ni < 4; ni++)
                        mma16816(acc[mi][ni],
                                 a[mi][0], a[mi][1], a[mi][2], a[mi][3],
                                 bf[ni >> 1][ni & 1], bf[ni >> 1][(ni & 1) + 2]);
            }
        }
        __syncthreads();
    }

    // epilogue: c0,c1 -> row lane/4, cols (lane%3)*2.. ; c2,c3 -> row+8
    const int r0 = lane >> 2;
    const int cc = (lane & 3) * 2;
    #pragma unroll
    for (int mi = 0; mi < 4; mi++) {
        #pragma unroll
        for (int ni = 0; ni < 4; ni++) {
            int col = (int)bn + wn * 32 + ni * 8 + cc;
            float2 bsv = *(const float2*)&bias[col];
            #pragma unroll
            for (int half = 0; half < 2; half++) {
                size_t m = bm + wm * 64 + mi * 16 + r0 + half * 8;
                float v0 = acc[mi][ni][half * 2 + 0] + bsv.x;
                float v1 = acc[mi][ni][half * 2 + 1] + bsv.y;
                float* dst;
                if (HEADSPLIT) {
                    size_t b_ = m >> 11, s_ = m & 2047;
                    int h = col >> 7, d = col & 127;
                    dst = out + ((b_ * NH + h) * Ssz + s_) * HD + d;
                } else {
                    dst = out + m * Hsz + col;
                }
                *(float2*)dst = make_float2(v0, v1);
            }
        }
    }
}

// ---------------- attention: register-blocked fp32 + fma.rn.f32x2 ---------
// Block: 64 q-rows of one head; 64-key tiles. 256 threads.
// Scores map: ty=tid>>4 -> q rows ty*4+i ; tx=tid&15 -> keys tx+16j.
// PV map:     r4=tid&15 -> q rows r4*4+i ; dg=tid>>4 -> dims dg*8..+7.
#define AP 132                 // Q/K/V row pitch (floats): 33 quads -> conflict-free
#define PP 68                  // P row pitch (floats): 17 quads
#define A_QS 0
#define A_KS (64*AP)
#define A_VS (2*64*AP)
#define A_PS (3*64*AP)
#define A_CR (A_PS + 64*PP)
#define A_LR (A_CR + 64)
#define A_SMEM ((A_LR + 64) * 4)

__global__ void __launch_bounds__(256, 1) attn_kernel(
    const float* __restrict__ Q, const float* __restrict__ K,
    const float* __restrict__ V, float* __restrict__ out)
{
    extern __shared__ float sm[];
    const int tid = threadIdx.x;
    const int ty = tid >> 4, tx = tid & 15;   // scores map
    const int r4 = tid & 15, dg = tid >> 4;   // PV map
    const int bh = blockIdx.y;
    const int q0 = blockIdx.x * 64;

    const float* Qh = Q + ((size_t)bh * Ssz + q0) * HD;
    const float* Kh = K + (size_t)bh * Ssz * HD;
    const float* Vh = V + (size_t)bh * Ssz * HD;

    // stage Q (64x128)
    #pragma unroll
    for (int i = 0; i < 8; i++) {
        int idx = tid + i * 256;
        int row = idx >> 5, c4 = idx & 31;
        *(float4*)&sm[A_QS + row * AP + c4 * 4] =
            *(const float4*)(Qh + (size_t)row * HD + c4 * 4);
    }

    const float scale = 0.08838834764831843f;
    float m_run[4], l_run[4];
    unsigned long long acc2[4][4];
    #pragma unroll
    for (int i = 0; i < 4; i++) {
        m_run[i] = -1e30f; l_run[i] = 0.f;
        #pragma unroll
        for (int j = 0; j < 4; j++) acc2[i][j] = 0ull;
    }

    for (int kt = 0; kt < Ssz; kt += 64) {
        __syncthreads();   // prev PV done (+ Q staged on first iter)
        #pragma unroll
        for (int i = 0; i < 8; i++) {
            int idx = tid + i * 256;
            int row = idx >> 5, c4 = idx & 31;
            *(float4*)&sm[A_KS + row * AP + c4 * 4] =
                *(const float4*)(Kh + (size_t)(kt + row) * HD + c4 * 4);
            *(float4*)&sm[A_VS + row * AP + c4 * 4] =
                *(const float4*)(Vh + (size_t)(kt + row) * HD + c4 * 4);
        }
        __syncthreads();

        // ---- scores: s(4q x 4key) over d=128, packed f32x2 ----
        unsigned long long s2[4][4];
        #pragma unroll
        for (int i = 0; i < 4; i++)
            #pragma unroll
            for (int j = 0; j < 4; j++) s2[i][j] = 0ull;
        #pragma unroll 8
        for (int d4 = 0; d4 < 32; d4++) {
            ulonglong2 q2[4], k2[4];
            #pragma unroll
            for (int i = 0; i < 4; i++)
                q2[i] = *(const ulonglong2*)&sm[A_QS + (ty * 4 + i) * AP + d4 * 4];
            #pragma unroll
            for (int j = 0; j < 4; j++)
                k2[j] = *(const ulonglong2*)&sm[A_KS + (tx + 16 * j) * AP + d4 * 4];
            #pragma unroll
            for (int i = 0; i < 4; i++)
                #pragma unroll
                for (int j = 0; j < 4; j++) {
                    FMA2(s2[i][j], q2[i].x, k2[j].x, s2[i][j]);
                    FMA2(s2[i][j], q2[i].y, k2[j].y, s2[i][j]);
                }
        }
        // ---- online softmax per q-row ----
        #pragma unroll
        for (int i = 0; i < 4; i++) {
            float s[4];
            #pragma unroll
            for (int j = 0; j < 4; j++) {
                float lo, hi; UNPK(lo, hi, s2[i][j]);
                s[j] = (lo + hi) * scale;
            }
            float mt = fmaxf(fmaxf(s[0], s[1]), fmaxf(s[2], s[3]));
            #pragma unroll
            for (int off = 8; off > 0; off >>= 1)
                mt = fmaxf(mt, __shfl_xor_sync(0xffffffffu, mt, off));
            float m_new = fmaxf(m_run[i], mt);
            float corr = __expf(m_run[i] - m_new);
            float p[4], ls = 0.f;
            #pragma unroll
            for (int j = 0; j < 4; j++) { p[j] = __expf(s[j] - m_new); ls += p[j]; }
            #pragma unroll
            for (int off = 8; off > 0; off >>= 1)
                ls += __shfl_xor_sync(0xffffffffu, ls, off);
            l_run[i] = l_run[i] * corr + ls;
            m_run[i] = m_new;
            if (tx == 0) sm[A_CR + ty * 4 + i] = corr;
            #pragma unroll
            for (int j = 0; j < 4; j++) s2[i][j] = __float_as_uint(p[j]); // stash p
        }
        // write P tile: Ps[key][q] (float4 of 4 q-rows per key)
        #pragma unroll
        for (int j = 0; j < 4; j++) {
            float4 pv;
            pv.x = __uint_as_float((unsigned)s2[0][j]);
            pv.y = __uint_as_float((unsigned)s2[1][j]);
            pv.z = __uint_as_float((unsigned)s2[2][j]);
            pv.w = __uint_as_float((unsigned)s2[3][j]);
            *(float4*)&sm[A_PS + (tx + 16 * j) * PP + ty * 4] = pv;
        }
        __syncthreads();

        // ---- PV: acc(4q x 8d) += P(4q x 64k) @ V(64k x 8d), packed ----
        #pragma unroll
        for (int i = 0; i < 4; i++) {
            float c = sm[A_CR + r4 * 4 + i];
            unsigned long long cc = pk2(c, c);
            #pragma unroll
            for (int j = 0; j < 4; j++) MUL2(acc2[i][j], acc2[i][j], cc);
        }
        #pragma unroll 8
        for (int key = 0; key < 64; key++) {
            float4 pv = *(const float4*)&sm[A_PS + key * PP + r4 * 4];
            ulonglong2 va = *(const ulonglong2*)&sm[A_VS + key * AP + dg * 8];
            ulonglong2 vb = *(const ulonglong2*)&sm[A_VS + key * AP + dg * 8 + 4];
            float pa[4] = { pv.x, pv.y, pv.z, pv.w };
            #pragma unroll
            for (int i = 0; i < 4; i++) {
                unsigned long long pp = pk2(pa[i], pa[i]);
                FMA2(acc2[i][0], pp, va.x, acc2[i][0]);
                FMA2(acc2[i][1], pp, va.y, acc2[i][1]);
                FMA2(acc2[i][2], pp, vb.x, acc2[i][2]);
                FMA2(acc2[i][3], pp, vb.y, acc2[i][3]);
            }
        }
    }

    if (tx == 0)
        #pragma unroll
        for (int i = 0; i < 4; i++) sm[A_LR + ty * 4 + i] = l_run[i];
    __syncthreads();

    const int b = bh / NH, h = bh % NH;
    #pragma unroll
    for (int i = 0; i < 4; i++) {
        float inv = 1.f / sm[A_LR + r4 * 4 + i];
        float o[8];
        #pragma unroll
        for (int j = 0; j < 4; j++) {
            float lo, hi; UNPK(lo, hi, acc2[i][j]);
            o[2 * j] = lo * inv; o[2 * j + 1] = hi * inv;
        }
        size_t s_ = q0 + r4 * 4 + i;
        float* dst = out + ((size_t)b * Ssz + s_) * Hsz + h * HD + dg * 8;
        *(float4*)dst = make_float4(o[0], o[1], o[2], o[3]);
        *(float4*)(dst + 4) = make_float4(o[4], o[5], o[6], o[7]);
    }
}

// ---------------------------------------------------------------------------
extern "C" void kernel_launch(void* const* d_in, const int* in_sizes, int n_in,
                              void* d_out, int out_size)
{
    const float* x  = (const float*)d_in[0];
    const float* Wq = (const float*)d_in[1];
    const float* bq = (const float*)d_in[2];
    const float* Wk = (const float*)d_in[3];
    const float* bk = (const float*)d_in[4];
    const float* Wv = (const float*)d_in[5];
    const float* bv = (const float*)d_in[6];
    const float* Wo = (const float*)d_in[7];
    const float* bo = (const float*)d_in[8];
    float* out = (float*)d_out;

    __nv_bfloat16 *xhi, *xlo, *whi, *wlo, *aohi, *aolo;
    float *q, *k, *v, *ao;
    cudaGetSymbolAddress((void**)&xhi, g_xhi);
    cudaGetSymbolAddress((void**)&xlo, g_xlo);
    cudaGetSymbolAddress((void**)&whi, g_whi);
    cudaGetSymbolAddress((void**)&wlo, g_wlo);
    cudaGetSymbolAddress((void**)&q,  g_q);
    cudaGetSymbolAddress((void**)&k,  g_k);
    cudaGetSymbolAddress((void**)&v,  g_v);
    cudaGetSymbolAddress((void**)&ao, g_ao);
    cudaGetSymbolAddress((void**)&aohi, g_aohi);
    cudaGetSymbolAddress((void**)&aolo, g_aolo);

    cudaFuncSetAttribute(gemm_mma<true>,  cudaFuncAttributeMaxDynamicSharedMemorySize, GSMEM);
    cudaFuncSetAttribute(gemm_mma<false>, cudaFuncAttributeMaxDynamicSharedMemorySize, GSMEM);
    cudaFuncSetAttribute(attn_kernel,     cudaFuncAttributeMaxDynamicSharedMemorySize, A_SMEM);

    dim3 tgrid(Hsz / 32, Hsz / 32), tblk(32, 8);
    tsplit_kernel<<<tgrid, tblk>>>(Wq, whi + 0 * WK, wlo + 0 * WK);
    tsplit_kernel<<<tgrid, tblk>>>(Wk, whi + 1 * WK, wlo + 1 * WK);
    tsplit_kernel<<<tgrid, tblk>>>(Wv, whi + 2 * WK, wlo + 2 * WK);
    tsplit_kernel<<<tgrid, tblk>>>(Wo, whi + 3 * WK, wlo + 3 * WK);
    split_kernel<<<2048, 256>>>(x, xhi, xlo, MK);

    dim3 ggrid(Hsz / 128, Msz / 128);   // (16, 64)
    gemm_mma<true><<<ggrid, 256, GSMEM>>>(xhi, xlo, whi + 0 * WK, wlo + 0 * WK, bq, q);
    gemm_mma<true><<<ggrid, 256, GSMEM>>>(xhi, xlo, whi + 1 * WK, wlo + 1 * WK, bk, k);
    gemm_mma<true><<<ggrid, 256, GSMEM>>>(xhi, xlo, whi + 2 * WK, wlo + 2 * WK, bv, v);

    dim3 agrid(Ssz / 64, Bsz * NH);     // (32, 64)
    attn_kernel<<<agrid, 256, A_SMEM>>>(q, k, v, ao);

    split_kernel<<<2048, 256>>>(ao, aohi, aolo, MK);
    gemm_mma<false><<<ggrid, 256, GSMEM>>>(aohi, aolo, whi + 3 * WK, wlo + 3 * WK, bo, out);
}

// round 5
// speedup vs baseline: 4.3856x; 1.5530x over previous
#include <cuda_runtime.h>
#include <cuda_bf16.h>
#include <math.h>

// Problem shape
#define Bsz 4
#define Ssz 2048
#define Hsz 2048
#define NH  16
#define HD  128
#define Msz (Bsz*Ssz)          // 8192
#define MK  ((size_t)Msz*Hsz)  // 16,777,216
#define WK  ((size_t)Hsz*Hsz)  // 4,194,304

#define QSCALE 0.08838834764831843f   // 1/sqrt(128)

// ---------------- scratch (__device__ globals; no cudaMalloc allowed) ------
__device__ __nv_bfloat16 g_xhi[MK], g_xlo[MK];
__device__ __nv_bfloat16 g_whi[4][WK], g_wlo[4][WK];   // W^T split, [N][K]
__device__ __nv_bfloat16 g_qh[MK], g_ql[MK];           // [B*nh][S][hd], scale folded
__device__ __nv_bfloat16 g_kh[MK], g_kl[MK];           // [B*nh][S][hd]
__device__ __nv_bfloat16 g_vth[MK], g_vtl[MK];         // V^T: [B*nh][hd][S]
__device__ __nv_bfloat16 g_aoh[MK], g_aol[MK];         // [B,S,H] split

// ---------------- PTX helpers ---------------------------------------------
__device__ __forceinline__ unsigned smem_u32(const void* p) {
    unsigned a;
    asm("{ .reg .u64 t; cvta.to.shared.u64 t, %1; cvt.u32.u64 %0, t; }"
        : "=r"(a) : "l"(p));
    return a;
}
__device__ __forceinline__ void ldsm_x4(unsigned& r0, unsigned& r1,
                                        unsigned& r2, unsigned& r3, unsigned a) {
    asm volatile("ldmatrix.sync.aligned.m8n8.x4.shared.b16 {%0,%1,%2,%3}, [%4];"
                 : "=r"(r0), "=r"(r1), "=r"(r2), "=r"(r3) : "r"(a));
}
__device__ __forceinline__ void mma16816(float* c, unsigned a0, unsigned a1,
                                         unsigned a2, unsigned a3,
                                         unsigned b0, unsigned b1) {
    asm volatile(
        "mma.sync.aligned.m16n8k16.row.col.f32.bf16.bf16.f32 "
        "{%0,%1,%2,%3}, {%4,%5,%6,%7}, {%8,%9}, {%0,%1,%2,%3};"
        : "+f"(c[0]), "+f"(c[1]), "+f"(c[2]), "+f"(c[3])
        : "r"(a0), "r"(a1), "r"(a2), "r"(a3), "r"(b0), "r"(b1));
}
__device__ __forceinline__ void cp16(unsigned dst, const void* src) {
    asm volatile("{ .reg .u64 g; cvta.to.global.u64 g, %1;\n\t"
                 "cp.async.cg.shared.global [%0], [g], 16; }"
                 :: "r"(dst), "l"(src) : "memory");
}
#define CP_COMMIT() asm volatile("cp.async.commit_group;" ::: "memory")
#define CP_WAIT1()  asm volatile("cp.async.wait_group 1;" ::: "memory")
#define CP_WAIT0()  asm volatile("cp.async.wait_group 0;" ::: "memory")

// split a float pair into hi/lo bf16x2 words
__device__ __forceinline__ void split2(float v0, float v1, unsigned& hi, unsigned& lo) {
    __nv_bfloat162 h = __float22bfloat162_rn(make_float2(v0, v1));
    hi = *(unsigned*)&h;
    float r0 = v0 - __bfloat162float(h.x);
    float r1 = v1 - __bfloat162float(h.y);
    __nv_bfloat162 l = __float22bfloat162_rn(make_float2(r0, r1));
    lo = *(unsigned*)&l;
}

// ---------------- conversion kernels --------------------------------------
__global__ void split_kernel(const float* __restrict__ in,
                             __nv_bfloat16* __restrict__ hi,
                             __nv_bfloat16* __restrict__ lo, size_t n) {
    for (size_t i = blockIdx.x * blockDim.x + threadIdx.x; i < n;
         i += (size_t)gridDim.x * blockDim.x) {
        float f = in[i];
        __nv_bfloat16 h = __float2bfloat16(f);
        hi[i] = h;
        lo[i] = __float2bfloat16(f - __bfloat162float(h));
    }
}

// W[K][N] -> Wt_hi/lo[N][K] (split bf16)
__global__ void tsplit_kernel(const float* __restrict__ W,
                              __nv_bfloat16* __restrict__ hi,
                              __nv_bfloat16* __restrict__ lo) {
    __shared__ float tile[32][33];
    int bx = blockIdx.x * 32, by = blockIdx.y * 32;
    int tx = threadIdx.x, ty = threadIdx.y;
    #pragma unroll
    for (int i = 0; i < 32; i += 8)
        tile[ty + i][tx] = W[(size_t)(by + ty + i) * Hsz + bx + tx];
    __syncthreads();
    #pragma unroll
    for (int i = 0; i < 32; i += 8) {
        int n = bx + ty + i, k = by + tx;
        float f = tile[tx][ty + i];
        __nv_bfloat16 h = __float2bfloat16(f);
        hi[(size_t)n * Hsz + k] = h;
        lo[(size_t)n * Hsz + k] = __float2bfloat16(f - __bfloat162float(h));
    }
}

// ---------------- mma.sync split-bf16 GEMM ---------------------------------
// C[M,N] = A@B^T + bias. Block 128x128, K-chunk 32, 8 warps 2x4, warp 64x32.
// MODE: 0 = fp32 out [M][N] (Wo). 1 = Q split bf16 headsplit + QSCALE.
//       2 = K split bf16 headsplit. 3 = V split bf16 TRANSPOSED [bh][d][s].
#define TPITCH 80
#define TILE_B (128*TPITCH)
#define BUF_B  (4*TILE_B)
#define GSMEM  (2*BUF_B)

__device__ __forceinline__ void gemm_issue(const __nv_bfloat16* const* src,
                                           unsigned sb, int buf, int k0, int tid) {
    #pragma unroll
    for (int t = 0; t < 4; t++) {
        #pragma unroll
        for (int i = 0; i < 2; i++) {
            int s = tid + i * 256;
            int row = s >> 2, sq = s & 3;
            unsigned d = sb + buf * BUF_B + t * TILE_B + row * TPITCH + sq * 16;
            cp16(d, src[t] + (size_t)row * Hsz + k0 + sq * 8);
        }
    }
    CP_COMMIT();
}

template<int MODE>
__global__ void __launch_bounds__(256, 1) gemm_mma(
    const __nv_bfloat16* __restrict__ Ah, const __nv_bfloat16* __restrict__ Al,
    const __nv_bfloat16* __restrict__ Bh, const __nv_bfloat16* __restrict__ Bl,
    const float* __restrict__ bias, float* __restrict__ outf,
    __nv_bfloat16* __restrict__ oh, __nv_bfloat16* __restrict__ ol)
{
    extern __shared__ char smc[];
    const unsigned sb = smem_u32(smc);
    const int tid = threadIdx.x, wid = tid >> 5, lane = tid & 31;
    const int wm = wid >> 2, wn = wid & 3;
    const size_t bm = (size_t)blockIdx.y * 128, bn = (size_t)blockIdx.x * 128;

    const __nv_bfloat16* src[4] = { Ah + bm * Hsz, Al + bm * Hsz,
                                    Bh + bn * Hsz, Bl + bn * Hsz };

    float acc[4][4][4];
    #pragma unroll
    for (int mi = 0; mi < 4; mi++)
        #pragma unroll
        for (int ni = 0; ni < 4; ni++)
            #pragma unroll
            for (int r = 0; r < 4; r++) acc[mi][ni][r] = 0.f;

    const unsigned lm_off = (unsigned)((lane & 15) * TPITCH + (lane >> 4) * 16);

    gemm_issue(src, sb, 0, 0, tid);

    #pragma unroll 1
    for (int c = 0; c < 64; c++) {
        const int buf = c & 1;
        if (c < 63) { gemm_issue(src, sb, buf ^ 1, (c + 1) * 32, tid); CP_WAIT1(); }
        else        { CP_WAIT0(); }
        __syncthreads();

        const unsigned base = sb + buf * BUF_B;
        #pragma unroll
        for (int pass = 0; pass < 3; pass++) {
            const unsigned abase = base + (pass == 2 ? TILE_B : 0u)
                                 + (unsigned)(wm * 64 * TPITCH) + lm_off;
            const unsigned bbase = base + 2u * TILE_B + (pass == 1 ? TILE_B : 0u)
                                 + (unsigned)(wn * 32 * TPITCH) + lm_off;
            #pragma unroll
            for (int ks = 0; ks < 2; ks++) {
                unsigned a[4][4], bf[2][4];
                #pragma unroll
                for (int mi = 0; mi < 4; mi++)
                    ldsm_x4(a[mi][0], a[mi][1], a[mi][2], a[mi][3],
                            abase + mi * 16 * TPITCH + ks * 32);
                #pragma unroll
                for (int bi = 0; bi < 2; bi++)
                    ldsm_x4(bf[bi][0], bf[bi][1], bf[bi][2], bf[bi][3],
                            bbase + bi * 16 * TPITCH + ks * 32);
                #pragma unroll
                for (int mi = 0; mi < 4; mi++)
                    #pragma unroll
                    for (int ni = 0; ni < 4; ni++)
                        mma16816(acc[mi][ni],
                                 a[mi][0], a[mi][1], a[mi][2], a[mi][3],
                                 bf[ni >> 1][ni & 1], bf[ni >> 1][(ni & 1) + 2]);
            }
        }
        __syncthreads();
    }

    const int r0 = lane >> 2;
    const int cc = (lane & 3) * 2;
    #pragma unroll
    for (int mi = 0; mi < 4; mi++) {
        #pragma unroll
        for (int ni = 0; ni < 4; ni++) {
            int col = (int)bn + wn * 32 + ni * 8 + cc;
            float2 bsv = *(const float2*)&bias[col];
            #pragma unroll
            for (int half = 0; half < 2; half++) {
                size_t m = bm + wm * 64 + mi * 16 + r0 + half * 8;
                float v0 = acc[mi][ni][half * 2 + 0] + bsv.x;
                float v1 = acc[mi][ni][half * 2 + 1] + bsv.y;
                if (MODE == 0) {
                    *(float2*)(outf + m * Hsz + col) = make_float2(v0, v1);
                } else {
                    if (MODE == 1) { v0 *= QSCALE; v1 *= QSCALE; }
                    unsigned hw, lw;
                    split2(v0, v1, hw, lw);
                    size_t b_ = m >> 11, s_ = m & 2047;
                    int hh = col >> 7, d = col & 127;
                    if (MODE <= 2) {
                        size_t idx = (((b_ * NH + hh) * Ssz) + s_) * HD + d;
                        *(unsigned*)(oh + idx) = hw;
                        *(unsigned*)(ol + idx) = lw;
                    } else {
                        size_t idx0 = ((b_ * NH + hh) * (size_t)HD + d) * Ssz + s_;
                        size_t idx1 = idx0 + Ssz;   // d+1
                        __nv_bfloat162 h2 = *(__nv_bfloat162*)&hw;
                        __nv_bfloat162 l2 = *(__nv_bfloat162*)&lw;
                        oh[idx0] = h2.x; oh[idx1] = h2.y;
                        ol[idx0] = l2.x; ol[idx1] = l2.y;
                    }
                }
            }
        }
    }
}

// ---------------- attention: mma.sync bf16 split, FA2-style ----------------
// Block: 128 q-rows of one head, 8 warps x 16 rows. 64-key tiles, double-buffered.
// Q/K smem pitch 272B (136 bf16), V^T pitch 144B (72 bf16) — 16B row-shift -> ldsm OK.
#define S_QH 0
#define S_QL 34816                 // 128*272
#define S_KV0 69632
#define S_KH 0
#define S_KL 17408                 // 64*272
#define S_VH 34816
#define S_VL 53248                 // +128*144
#define KVBUF 71680
#define A_SMEM (S_KV0 + 2*KVBUF)   // 212992

__device__ __forceinline__ void attn_issue_kv(
    unsigned sb, int buf, int t, int tid,
    const __nv_bfloat16* kh, const __nv_bfloat16* kl,
    const __nv_bfloat16* vth, const __nv_bfloat16* vtl)
{
    unsigned kb = sb + S_KV0 + buf * KVBUF;
    #pragma unroll
    for (int i = 0; i < 4; i++) {
        int idx = tid + i * 256; int row = idx >> 4, ch = idx & 15;
        cp16(kb + S_KH + row * 272 + ch * 16, kh + (size_t)(t * 64 + row) * HD + ch * 8);
        cp16(kb + S_KL + row * 272 + ch * 16, kl + (size_t)(t * 64 + row) * HD + ch * 8);
    }
    #pragma unroll
    for (int i = 0; i < 4; i++) {
        int idx = tid + i * 256; int row = idx >> 3, ch = idx & 7;
        cp16(kb + S_VH + row * 144 + ch * 16, vth + (size_t)row * Ssz + t * 64 + ch * 8);
        cp16(kb + S_VL + row * 144 + ch * 16, vtl + (size_t)row * Ssz + t * 64 + ch * 8);
    }
    CP_COMMIT();
}

__global__ void __launch_bounds__(256, 1) attn_mma(
    const __nv_bfloat16* __restrict__ Qhg, const __nv_bfloat16* __restrict__ Qlg,
    const __nv_bfloat16* __restrict__ Khg, const __nv_bfloat16* __restrict__ Klg,
    const __nv_bfloat16* __restrict__ Vthg, const __nv_bfloat16* __restrict__ Vtlg,
    __nv_bfloat16* __restrict__ AOh, __nv_bfloat16* __restrict__ AOl)
{
    extern __shared__ char smc[];
    const unsigned sb = smem_u32(smc);
    const int tid = threadIdx.x, w = tid >> 5, lane = tid & 31;
    const int bh = blockIdx.y, q0 = blockIdx.x * 128;

    const __nv_bfloat16* qh = Qhg + ((size_t)bh * Ssz + q0) * HD;
    const __nv_bfloat16* ql = Qlg + ((size_t)bh * Ssz + q0) * HD;
    const __nv_bfloat16* kh = Khg + (size_t)bh * Ssz * HD;
    const __nv_bfloat16* kl = Klg + (size_t)bh * Ssz * HD;
    const __nv_bfloat16* vth = Vthg + (size_t)bh * HD * Ssz;
    const __nv_bfloat16* vtl = Vtlg + (size_t)bh * HD * Ssz;

    // group 0: Q (one-time) + KV tile 0
    #pragma unroll
    for (int i = 0; i < 8; i++) {
        int idx = tid + i * 256; int row = idx >> 4, ch = idx & 15;
        cp16(sb + S_QH + row * 272 + ch * 16, qh + (size_t)row * HD + ch * 8);
        cp16(sb + S_QL + row * 272 + ch * 16, ql + (size_t)row * HD + ch * 8);
    }
    attn_issue_kv(sb, 0, 0, tid, kh, kl, vth, vtl);

    float m0 = -1e30f, m1 = -1e30f, l0 = 0.f, l1 = 0.f;
    float o[16][4];
    #pragma unroll
    for (int nf = 0; nf < 16; nf++)
        #pragma unroll
        for (int r = 0; r < 4; r++) o[nf][r] = 0.f;

    const unsigned lrow = (unsigned)(lane & 15);
    const unsigned lquad = (unsigned)((lane >> 4) * 16);
    const unsigned aqh = sb + S_QH + (w * 16 + lrow) * 272 + lquad;
    const unsigned aql = sb + S_QL + (w * 16 + lrow) * 272 + lquad;

    #pragma unroll 1
    for (int t = 0; t < 32; t++) {
        const int buf = t & 1;
        if (t < 31) { attn_issue_kv(sb, buf ^ 1, t + 1, tid, kh, kl, vth, vtl); CP_WAIT1(); }
        else        { CP_WAIT0(); }
        __syncthreads();

        const unsigned kb = sb + S_KV0 + buf * KVBUF;

        // ---- S = Q K^T (3-pass split) ----
        float s[8][4];
        #pragma unroll
        for (int nf = 0; nf < 8; nf++)
            #pragma unroll
            for (int r = 0; r < 4; r++) s[nf][r] = 0.f;

        #pragma unroll
        for (int kc = 0; kc < 8; kc++) {
            unsigned ah[4], al[4];
            ldsm_x4(ah[0], ah[1], ah[2], ah[3], aqh + kc * 32);
            ldsm_x4(al[0], al[1], al[2], al[3], aql + kc * 32);
            #pragma unroll
            for (int bi = 0; bi < 4; bi++) {
                unsigned kbr = (unsigned)(bi * 16 + lrow) * 272 + lquad + kc * 32;
                unsigned bh4[4], bl4[4];
                ldsm_x4(bh4[0], bh4[1], bh4[2], bh4[3], kb + S_KH + kbr);
                ldsm_x4(bl4[0], bl4[1], bl4[2], bl4[3], kb + S_KL + kbr);
                mma16816(s[2*bi],   ah[0],ah[1],ah[2],ah[3], bh4[0], bh4[2]);
                mma16816(s[2*bi+1], ah[0],ah[1],ah[2],ah[3], bh4[1], bh4[3]);
                mma16816(s[2*bi],   ah[0],ah[1],ah[2],ah[3], bl4[0], bl4[2]);
                mma16816(s[2*bi+1], ah[0],ah[1],ah[2],ah[3], bl4[1], bl4[3]);
                mma16816(s[2*bi],   al[0],al[1],al[2],al[3], bh4[0], bh4[2]);
                mma16816(s[2*bi+1], al[0],al[1],al[2],al[3], bh4[1], bh4[3]);
            }
        }

        // ---- online softmax (rows r0 = lane>>2 and r0+8) ----
        float mx0 = -1e30f, mx1 = -1e30f;
        #pragma unroll
        for (int nf = 0; nf < 8; nf++) {
            mx0 = fmaxf(mx0, fmaxf(s[nf][0], s[nf][1]));
            mx1 = fmaxf(mx1, fmaxf(s[nf][2], s[nf][3]));
        }
        mx0 = fmaxf(mx0, __shfl_xor_sync(0xffffffffu, mx0, 1));
        mx0 = fmaxf(mx0, __shfl_xor_sync(0xffffffffu, mx0, 2));
        mx1 = fmaxf(mx1, __shfl_xor_sync(0xffffffffu, mx1, 1));
        mx1 = fmaxf(mx1, __shfl_xor_sync(0xffffffffu, mx1, 2));
        float mn0 = fmaxf(m0, mx0), mn1 = fmaxf(m1, mx1);
        float c0 = __expf(m0 - mn0), c1 = __expf(m1 - mn1);
        m0 = mn0; m1 = mn1;
        float ls0 = 0.f, ls1 = 0.f;
        #pragma unroll
        for (int nf = 0; nf < 8; nf++) {
            s[nf][0] = __expf(s[nf][0] - mn0); ls0 += s[nf][0];
            s[nf][1] = __expf(s[nf][1] - mn0); ls0 += s[nf][1];
            s[nf][2] = __expf(s[nf][2] - mn1); ls1 += s[nf][2];
            s[nf][3] = __expf(s[nf][3] - mn1); ls1 += s[nf][3];
        }
        ls0 += __shfl_xor_sync(0xffffffffu, ls0, 1);
        ls0 += __shfl_xor_sync(0xffffffffu, ls0, 2);
        ls1 += __shfl_xor_sync(0xffffffffu, ls1, 1);
        ls1 += __shfl_xor_sync(0xffffffffu, ls1, 2);
        l0 = l0 * c0 + ls0;
        l1 = l1 * c1 + ls1;
        #pragma unroll
        for (int nf = 0; nf < 16; nf++) {
            o[nf][0] *= c0; o[nf][1] *= c0;
            o[nf][2] *= c1; o[nf][3] *= c1;
        }

        // ---- P -> bf16 split A-frags ----
        unsigned pah[4][4], pal[4][4];
        #pragma unroll
        for (int kc2 = 0; kc2 < 4; kc2++) {
            #pragma unroll
            for (int r = 0; r < 4; r++) {
                int nf = 2 * kc2 + (r >> 1);
                float v0 = s[nf][(r & 1) * 2], v1 = s[nf][(r & 1) * 2 + 1];
                split2(v0, v1, pah[kc2][r], pal[kc2][r]);
            }
        }

        // ---- O += P V (3-pass split), V^T in smem [dim][key] ----
        #pragma unroll
        for (int kc2 = 0; kc2 < 4; kc2++) {
            #pragma unroll
            for (int nf2 = 0; nf2 < 8; nf2++) {
                unsigned vr = (unsigned)(nf2 * 16 + lrow) * 144 + lquad + kc2 * 32;
                unsigned vh4[4], vl4[4];
                ldsm_x4(vh4[0], vh4[1], vh4[2], vh4[3], kb + S_VH + vr);
                ldsm_x4(vl4[0], vl4[1], vl4[2], vl4[3], kb + S_VL + vr);
                mma16816(o[2*nf2],   pah[kc2][0],pah[kc2][1],pah[kc2][2],pah[kc2][3], vh4[0], vh4[2]);
                mma16816(o[2*nf2+1], pah[kc2][0],pah[kc2][1],pah[kc2][2],pah[kc2][3], vh4[1], vh4[3]);
                mma16816(o[2*nf2],   pah[kc2][0],pah[kc2][1],pah[kc2][2],pah[kc2][3], vl4[0], vl4[2]);
                mma16816(o[2*nf2+1], pah[kc2][0],pah[kc2][1],pah[kc2][2],pah[kc2][3], vl4[1], vl4[3]);
                mma16816(o[2*nf2],   pal[kc2][0],pal[kc2][1],pal[kc2][2],pal[kc2][3], vh4[0], vh4[2]);
                mma16816(o[2*nf2+1], pal[kc2][0],pal[kc2][1],pal[kc2][2],pal[kc2][3], vh4[1], vh4[3]);
            }
        }
        __syncthreads();
    }

    // ---- epilogue: normalize, split, store to ao [B,S,H] ----
    float il0 = 1.f / l0, il1 = 1.f / l1;
    const int b = bh >> 4, h = bh & 15;
    size_t srow = (size_t)q0 + w * 16 + (lane >> 2);
    size_t base0 = ((size_t)b * Ssz + srow) * Hsz + h * 128 + (lane & 3) * 2;
    size_t base1 = base0 + 8 * (size_t)Hsz;
    #pragma unroll
    for (int nf = 0; nf < 16; nf++) {
        unsigned hw, lw;
        split2(o[nf][0] * il0, o[nf][1] * il0, hw, lw);
        *(unsigned*)(AOh + base0 + nf * 8) = hw;
        *(unsigned*)(AOl + base0 + nf * 8) = lw;
        split2(o[nf][2] * il1, o[nf][3] * il1, hw, lw);
        *(unsigned*)(AOh + base1 + nf * 8) = hw;
        *(unsigned*)(AOl + base1 + nf * 8) = lw;
    }
}

// ---------------------------------------------------------------------------
extern "C" void kernel_launch(void* const* d_in, const int* in_sizes, int n_in,
                              void* d_out, int out_size)
{
    const float* x  = (const float*)d_in[0];
    const float* Wq = (const float*)d_in[1];
    const float* bq = (const float*)d_in[2];
    const float* Wk = (const float*)d_in[3];
    const float* bk = (const float*)d_in[4];
    const float* Wv = (const float*)d_in[5];
    const float* bv = (const float*)d_in[6];
    const float* Wo = (const float*)d_in[7];
    const float* bo = (const float*)d_in[8];
    float* out = (float*)d_out;

    __nv_bfloat16 *xhi, *xlo, *whi, *wlo, *qh, *ql, *kh, *kl, *vth, *vtl, *aoh, *aol;
    cudaGetSymbolAddress((void**)&xhi, g_xhi);
    cudaGetSymbolAddress((void**)&xlo, g_xlo);
    cudaGetSymbolAddress((void**)&whi, g_whi);
    cudaGetSymbolAddress((void**)&wlo, g_wlo);
    cudaGetSymbolAddress((void**)&qh,  g_qh);
    cudaGetSymbolAddress((void**)&ql,  g_ql);
    cudaGetSymbolAddress((void**)&kh,  g_kh);
    cudaGetSymbolAddress((void**)&kl,  g_kl);
    cudaGetSymbolAddress((void**)&vth, g_vth);
    cudaGetSymbolAddress((void**)&vtl, g_vtl);
    cudaGetSymbolAddress((void**)&aoh, g_aoh);
    cudaGetSymbolAddress((void**)&aol, g_aol);

    cudaFuncSetAttribute(gemm_mma<0>, cudaFuncAttributeMaxDynamicSharedMemorySize, GSMEM);
    cudaFuncSetAttribute(gemm_mma<1>, cudaFuncAttributeMaxDynamicSharedMemorySize, GSMEM);
    cudaFuncSetAttribute(gemm_mma<2>, cudaFuncAttributeMaxDynamicSharedMemorySize, GSMEM);
    cudaFuncSetAttribute(gemm_mma<3>, cudaFuncAttributeMaxDynamicSharedMemorySize, GSMEM);
    cudaFuncSetAttribute(attn_mma,    cudaFuncAttributeMaxDynamicSharedMemorySize, A_SMEM);

    dim3 tgrid(Hsz / 32, Hsz / 32), tblk(32, 8);
    tsplit_kernel<<<tgrid, tblk>>>(Wq, whi + 0 * WK, wlo + 0 * WK);
    tsplit_kernel<<<tgrid, tblk>>>(Wk, whi + 1 * WK, wlo + 1 * WK);
    tsplit_kernel<<<tgrid, tblk>>>(Wv, whi + 2 * WK, wlo + 2 * WK);
    tsplit_kernel<<<tgrid, tblk>>>(Wo, whi + 3 * WK, wlo + 3 * WK);
    split_kernel<<<2048, 256>>>(x, xhi, xlo, MK);

    dim3 ggrid(Hsz / 128, Msz / 128);   // (16, 64)
    gemm_mma<1><<<ggrid, 256, GSMEM>>>(xhi, xlo, whi + 0 * WK, wlo + 0 * WK, bq,
                                       nullptr, qh, ql);
    gemm_mma<2><<<ggrid, 256, GSMEM>>>(xhi, xlo, whi + 1 * WK, wlo + 1 * WK, bk,
                                       nullptr, kh, kl);
    gemm_mma<3><<<ggrid, 256, GSMEM>>>(xhi, xlo, whi + 2 * WK, wlo + 2 * WK, bv,
                                       nullptr, vth, vtl);

    dim3 agrid(Ssz / 128, Bsz * NH);    // (16, 64)
    attn_mma<<<agrid, 256, A_SMEM>>>(qh, ql, kh, kl, vth, vtl, aoh, aol);

    gemm_mma<0><<<ggrid, 256, GSMEM>>>(aoh, aol, whi + 3 * WK, wlo + 3 * WK, bo,
                                       out, nullptr, nullptr);
}

// round 6
// speedup vs baseline: 4.5008x; 1.0263x over previous
#include <cuda_runtime.h>
#include <cuda_bf16.h>
#include <math.h>

// Problem shape
#define Bsz 4
#define Ssz 2048
#define Hsz 2048
#define NH  16
#define HD  128
#define Msz (Bsz*Ssz)          // 8192
#define MK  ((size_t)Msz*Hsz)  // 16,777,216
#define WK  ((size_t)Hsz*Hsz)  // 4,194,304

#define QSCALE 0.08838834764831843f   // 1/sqrt(128)

// ---------------- scratch (__device__ globals; no cudaMalloc allowed) ------
__device__ __nv_bfloat16 g_xhi[MK], g_xlo[MK];
__device__ __nv_bfloat16 g_whi[4][WK], g_wlo[4][WK];   // W^T split, [N][K]
__device__ __nv_bfloat16 g_qh[MK], g_ql[MK];           // [B*nh][S][hd], scale folded
__device__ __nv_bfloat16 g_kh[MK], g_kl[MK];           // [B*nh][S][hd]
__device__ __nv_bfloat16 g_vth[MK], g_vtl[MK];         // V^T: [B*nh][hd][S]
__device__ __nv_bfloat16 g_aoh[MK], g_aol[MK];         // [B,S,H] split

// ---------------- PTX helpers ---------------------------------------------
__device__ __forceinline__ unsigned smem_u32(const void* p) {
    unsigned a;
    asm("{ .reg .u64 t; cvta.to.shared.u64 t, %1; cvt.u32.u64 %0, t; }"
        : "=r"(a) : "l"(p));
    return a;
}
__device__ __forceinline__ void ldsm_x4(unsigned& r0, unsigned& r1,
                                        unsigned& r2, unsigned& r3, unsigned a) {
    asm volatile("ldmatrix.sync.aligned.m8n8.x4.shared.b16 {%0,%1,%2,%3}, [%4];"
                 : "=r"(r0), "=r"(r1), "=r"(r2), "=r"(r3) : "r"(a));
}
__device__ __forceinline__ void mma16816(float* c, unsigned a0, unsigned a1,
                                         unsigned a2, unsigned a3,
                                         unsigned b0, unsigned b1) {
    asm volatile(
        "mma.sync.aligned.m16n8k16.row.col.f32.bf16.bf16.f32 "
        "{%0,%1,%2,%3}, {%4,%5,%6,%7}, {%8,%9}, {%0,%1,%2,%3};"
        : "+f"(c[0]), "+f"(c[1]), "+f"(c[2]), "+f"(c[3])
        : "r"(a0), "r"(a1), "r"(a2), "r"(a3), "r"(b0), "r"(b1));
}
__device__ __forceinline__ void cp16(unsigned dst, const void* src) {
    asm volatile("{ .reg .u64 g; cvta.to.global.u64 g, %1;\n\t"
                 "cp.async.cg.shared.global [%0], [g], 16; }"
                 :: "r"(dst), "l"(src) : "memory");
}
#define CP_COMMIT() asm volatile("cp.async.commit_group;" ::: "memory")
#define CP_WAIT1()  asm volatile("cp.async.wait_group 1;" ::: "memory")
#define CP_WAIT0()  asm volatile("cp.async.wait_group 0;" ::: "memory")

// split a float pair into hi/lo bf16x2 words
__device__ __forceinline__ void split2(float v0, float v1, unsigned& hi, unsigned& lo) {
    __nv_bfloat162 h = __float22bfloat162_rn(make_float2(v0, v1));
    hi = *(unsigned*)&h;
    float r0 = v0 - __bfloat162float(h.x);
    float r1 = v1 - __bfloat162float(h.y);
    __nv_bfloat162 l = __float22bfloat162_rn(make_float2(r0, r1));
    lo = *(unsigned*)&l;
}

// ---------------- conversion kernels --------------------------------------
__global__ void split_kernel(const float* __restrict__ in,
                             __nv_bfloat16* __restrict__ hi,
                             __nv_bfloat16* __restrict__ lo, size_t n) {
    for (size_t i = blockIdx.x * blockDim.x + threadIdx.x; i < n;
         i += (size_t)gridDim.x * blockDim.x) {
        float f = in[i];
        __nv_bfloat16 h = __float2bfloat16(f);
        hi[i] = h;
        lo[i] = __float2bfloat16(f - __bfloat162float(h));
    }
}

// All 4 weight transposes in one launch: W[K][N] -> Wt_hi/lo[N][K], z selects W
__global__ void tsplit4_kernel(const float* __restrict__ W0, const float* __restrict__ W1,
                               const float* __restrict__ W2, const float* __restrict__ W3,
                               __nv_bfloat16* __restrict__ hib,
                               __nv_bfloat16* __restrict__ lob) {
    __shared__ float tile[32][33];
    const float* W = (blockIdx.z == 0) ? W0 : (blockIdx.z == 1) ? W1
                     : (blockIdx.z == 2) ? W2 : W3;
    __nv_bfloat16* hi = hib + (size_t)blockIdx.z * WK;
    __nv_bfloat16* lo = lob + (size_t)blockIdx.z * WK;
    int bx = blockIdx.x * 32, by = blockIdx.y * 32;
    int tx = threadIdx.x, ty = threadIdx.y;
    #pragma unroll
    for (int i = 0; i < 32; i += 8)
        tile[ty + i][tx] = W[(size_t)(by + ty + i) * Hsz + bx + tx];
    __syncthreads();
    #pragma unroll
    for (int i = 0; i < 32; i += 8) {
        int n = bx + ty + i, k = by + tx;
        float f = tile[tx][ty + i];
        __nv_bfloat16 h = __float2bfloat16(f);
        hi[(size_t)n * Hsz + k] = h;
        lo[(size_t)n * Hsz + k] = __float2bfloat16(f - __bfloat162float(h));
    }
}

// ---------------- mma.sync split-bf16 GEMM ---------------------------------
// C[M,N] = A@B^T + bias. Block 128x128, K-chunk 32, 8 warps 2x4, warp 64x32.
// MODE: 0 = fp32 out [M][N] (Wo). 1 = Q split bf16 headsplit + QSCALE.
//       2 = K split bf16 headsplit. 3 = V split bf16 TRANSPOSED [bh][d][s].
#define TPITCH 80
#define TILE_B (128*TPITCH)
#define BUF_B  (4*TILE_B)
#define GSMEM  (2*BUF_B)

__device__ __forceinline__ void gemm_issue(const __nv_bfloat16* const* src,
                                           unsigned sb, int buf, int k0, int tid) {
    #pragma unroll
    for (int t = 0; t < 4; t++) {
        #pragma unroll
        for (int i = 0; i < 2; i++) {
            int s = tid + i * 256;
            int row = s >> 2, sq = s & 3;
            unsigned d = sb + buf * BUF_B + t * TILE_B + row * TPITCH + sq * 16;
            cp16(d, src[t] + (size_t)row * Hsz + k0 + sq * 8);
        }
    }
    CP_COMMIT();
}

template<int MODE>
__global__ void __launch_bounds__(256, 1) gemm_mma(
    const __nv_bfloat16* __restrict__ Ah, const __nv_bfloat16* __restrict__ Al,
    const __nv_bfloat16* __restrict__ Bh, const __nv_bfloat16* __restrict__ Bl,
    const float* __restrict__ bias, float* __restrict__ outf,
    __nv_bfloat16* __restrict__ oh, __nv_bfloat16* __restrict__ ol)
{
    extern __shared__ char smc[];
    const unsigned sb = smem_u32(smc);
    const int tid = threadIdx.x, wid = tid >> 5, lane = tid & 31;
    const int wm = wid >> 2, wn = wid & 3;
    const size_t bm = (size_t)blockIdx.y * 128, bn = (size_t)blockIdx.x * 128;

    const __nv_bfloat16* src[4] = { Ah + bm * Hsz, Al + bm * Hsz,
                                    Bh + bn * Hsz, Bl + bn * Hsz };

    float acc[4][4][4];
    #pragma unroll
    for (int mi = 0; mi < 4; mi++)
        #pragma unroll
        for (int ni = 0; ni < 4; ni++)
            #pragma unroll
            for (int r = 0; r < 4; r++) acc[mi][ni][r] = 0.f;

    const unsigned lm_off = (unsigned)((lane & 15) * TPITCH + (lane >> 4) * 16);

    gemm_issue(src, sb, 0, 0, tid);

    #pragma unroll 1
    for (int c = 0; c < 64; c++) {
        const int buf = c & 1;
        if (c < 63) { gemm_issue(src, sb, buf ^ 1, (c + 1) * 32, tid); CP_WAIT1(); }
        else        { CP_WAIT0(); }
        __syncthreads();

        const unsigned base   = sb + buf * BUF_B;
        const unsigned a_hi_b = base + (unsigned)(wm * 64 * TPITCH) + lm_off;
        const unsigned a_lo_b = a_hi_b + TILE_B;
        const unsigned b_hi_b = base + 2u * TILE_B + (unsigned)(wn * 32 * TPITCH) + lm_off;
        const unsigned b_lo_b = b_hi_b + TILE_B;

        #pragma unroll
        for (int ks = 0; ks < 2; ks++) {
            unsigned ah[4][4], al[4][4], bh[2][4], bl[2][4];
            #pragma unroll
            for (int mi = 0; mi < 4; mi++)
                ldsm_x4(ah[mi][0], ah[mi][1], ah[mi][2], ah[mi][3],
                        a_hi_b + mi * 16 * TPITCH + ks * 32);
            #pragma unroll
            for (int mi = 0; mi < 4; mi++)
                ldsm_x4(al[mi][0], al[mi][1], al[mi][2], al[mi][3],
                        a_lo_b + mi * 16 * TPITCH + ks * 32);
            #pragma unroll
            for (int bi = 0; bi < 2; bi++) {
                ldsm_x4(bh[bi][0], bh[bi][1], bh[bi][2], bh[bi][3],
                        b_hi_b + bi * 16 * TPITCH + ks * 32);
                ldsm_x4(bl[bi][0], bl[bi][1], bl[bi][2], bl[bi][3],
                        b_lo_b + bi * 16 * TPITCH + ks * 32);
            }
            // fused 3-pass: Ah*Bh + Ah*Bl + Al*Bh (frags loaded once)
            #pragma unroll
            for (int mi = 0; mi < 4; mi++)
                #pragma unroll
                for (int ni = 0; ni < 4; ni++)
                    mma16816(acc[mi][ni], ah[mi][0], ah[mi][1], ah[mi][2], ah[mi][3],
                             bh[ni >> 1][ni & 1], bh[ni >> 1][(ni & 1) + 2]);
            #pragma unroll
            for (int mi = 0; mi < 4; mi++)
                #pragma unroll
                for (int ni = 0; ni < 4; ni++)
                    mma16816(acc[mi][ni], ah[mi][0], ah[mi][1], ah[mi][2], ah[mi][3],
                             bl[ni >> 1][ni & 1], bl[ni >> 1][(ni & 1) + 2]);
            #pragma unroll
            for (int mi = 0; mi < 4; mi++)
                #pragma unroll
                for (int ni = 0; ni < 4; ni++)
                    mma16816(acc[mi][ni], al[mi][0], al[mi][1], al[mi][2], al[mi][3],
                             bh[ni >> 1][ni & 1], bh[ni >> 1][(ni & 1) + 2]);
        }
        __syncthreads();
    }

    const int r0 = lane >> 2;
    const int cc = (lane & 3) * 2;

    if (MODE == 3) {
        // stage tile as V^T [d][s] in smem, then coalesced 16B stores.
        unsigned short* sh = (unsigned short*)smc;          // 128 x 136 u16
        unsigned short* sl = sh + 128 * 136;
        #pragma unroll
        for (int mi = 0; mi < 4; mi++) {
            #pragma unroll
            for (int ni = 0; ni < 4; ni++) {
                int cl = wn * 32 + ni * 8 + cc;             // local d
                float2 bsv = *(const float2*)&bias[bn + cl];
                #pragma unroll
                for (int half = 0; half < 2; half++) {
                    int ml = wm * 64 + mi * 16 + r0 + half * 8;   // local s
                    float v0 = acc[mi][ni][half * 2 + 0] + bsv.x;
                    float v1 = acc[mi][ni][half * 2 + 1] + bsv.y;
                    unsigned hw, lw;
                    split2(v0, v1, hw, lw);
                    __nv_bfloat162 h2 = *(__nv_bfloat162*)&hw;
                    __nv_bfloat162 l2 = *(__nv_bfloat162*)&lw;
                    sh[(cl + 0) * 136 + ml] = *(unsigned short*)&h2.x;
                    sh[(cl + 1) * 136 + ml] = *(unsigned short*)&h2.y;
                    sl[(cl + 0) * 136 + ml] = *(unsigned short*)&l2.x;
                    sl[(cl + 1) * 136 + ml] = *(unsigned short*)&l2.y;
                }
            }
        }
        __syncthreads();
        const int hh = (int)(bn >> 7);
        const size_t b_ = bm >> 11, sbase = bm & 2047;
        const size_t rowbase = ((b_ * NH + hh) * (size_t)HD);
        #pragma unroll
        for (int i = 0; i < 8; i++) {
            int idx = tid + i * 256;        // 0..2047
            int d = idx >> 4, ch = idx & 15;
            uint4 vh = *(uint4*)(sh + d * 136 + ch * 8);
            uint4 vl = *(uint4*)(sl + d * 136 + ch * 8);
            size_t off = (rowbase + d) * Ssz + sbase + ch * 8;
            *(uint4*)(oh + off) = vh;
            *(uint4*)(ol + off) = vl;
        }
        return;
    }

    #pragma unroll
    for (int mi = 0; mi < 4; mi++) {
        #pragma unroll
        for (int ni = 0; ni < 4; ni++) {
            int col = (int)bn + wn * 32 + ni * 8 + cc;
            float2 bsv = *(const float2*)&bias[col];
            #pragma unroll
            for (int half = 0; half < 2; half++) {
                size_t m = bm + wm * 64 + mi * 16 + r0 + half * 8;
                float v0 = acc[mi][ni][half * 2 + 0] + bsv.x;
                float v1 = acc[mi][ni][half * 2 + 1] + bsv.y;
                if (MODE == 0) {
                    *(float2*)(outf + m * Hsz + col) = make_float2(v0, v1);
                } else {
                    if (MODE == 1) { v0 *= QSCALE; v1 *= QSCALE; }
                    unsigned hw, lw;
                    split2(v0, v1, hw, lw);
                    size_t b_ = m >> 11, s_ = m & 2047;
                    int hh = col >> 7, d = col & 127;
                    size_t idx = (((b_ * NH + hh) * Ssz) + s_) * HD + d;
                    *(unsigned*)(oh + idx) = hw;
                    *(unsigned*)(ol + idx) = lw;
                }
            }
        }
    }
}

// ---------------- attention: mma.sync bf16 split, FA2-style ----------------
// Block: 128 q-rows of one head, 8 warps x 16 rows. 64-key tiles, double-buffered.
// Q/K smem pitch 272B (136 bf16), V^T pitch 144B (72 bf16).
#define S_QH 0
#define S_QL 34816                 // 128*272
#define S_KV0 69632
#define S_KH 0
#define S_KL 17408                 // 64*272
#define S_VH 34816
#define S_VL 53248                 // +128*144
#define KVBUF 71680
#define A_SMEM (S_KV0 + 2*KVBUF)   // 212992

__device__ __forceinline__ void attn_issue_kv(
    unsigned sb, int buf, int t, int tid,
    const __nv_bfloat16* kh, const __nv_bfloat16* kl,
    const __nv_bfloat16* vth, const __nv_bfloat16* vtl)
{
    unsigned kb = sb + S_KV0 + buf * KVBUF;
    #pragma unroll
    for (int i = 0; i < 4; i++) {
        int idx = tid + i * 256; int row = idx >> 4, ch = idx & 15;
        cp16(kb + S_KH + row * 272 + ch * 16, kh + (size_t)(t * 64 + row) * HD + ch * 8);
        cp16(kb + S_KL + row * 272 + ch * 16, kl + (size_t)(t * 64 + row) * HD + ch * 8);
    }
    #pragma unroll
    for (int i = 0; i < 4; i++) {
        int idx = tid + i * 256; int row = idx >> 3, ch = idx & 7;
        cp16(kb + S_VH + row * 144 + ch * 16, vth + (size_t)row * Ssz + t * 64 + ch * 8);
        cp16(kb + S_VL + row * 144 + ch * 16, vtl + (size_t)row * Ssz + t * 64 + ch * 8);
    }
    CP_COMMIT();
}

__global__ void __launch_bounds__(256, 1) attn_mma(
    const __nv_bfloat16* __restrict__ Qhg, const __nv_bfloat16* __restrict__ Qlg,
    const __nv_bfloat16* __restrict__ Khg, const __nv_bfloat16* __restrict__ Klg,
    const __nv_bfloat16* __restrict__ Vthg, const __nv_bfloat16* __restrict__ Vtlg,
    __nv_bfloat16* __restrict__ AOh, __nv_bfloat16* __restrict__ AOl)
{
    extern __shared__ char smc[];
    const unsigned sb = smem_u32(smc);
    const int tid = threadIdx.x, w = tid >> 5, lane = tid & 31;
    const int bh = blockIdx.y, q0 = blockIdx.x * 128;

    const __nv_bfloat16* qh = Qhg + ((size_t)bh * Ssz + q0) * HD;
    const __nv_bfloat16* ql = Qlg + ((size_t)bh * Ssz + q0) * HD;
    const __nv_bfloat16* kh = Khg + (size_t)bh * Ssz * HD;
    const __nv_bfloat16* kl = Klg + (size_t)bh * Ssz * HD;
    const __nv_bfloat16* vth = Vthg + (size_t)bh * HD * Ssz;
    const __nv_bfloat16* vtl = Vtlg + (size_t)bh * HD * Ssz;

    #pragma unroll
    for (int i = 0; i < 8; i++) {
        int idx = tid + i * 256; int row = idx >> 4, ch = idx & 15;
        cp16(sb + S_QH + row * 272 + ch * 16, qh + (size_t)row * HD + ch * 8);
        cp16(sb + S_QL + row * 272 + ch * 16, ql + (size_t)row * HD + ch * 8);
    }
    attn_issue_kv(sb, 0, 0, tid, kh, kl, vth, vtl);

    float m0 = -1e30f, m1 = -1e30f, l0 = 0.f, l1 = 0.f;
    float o[16][4];
    #pragma unroll
    for (int nf = 0; nf < 16; nf++)
        #pragma unroll
        for (int r = 0; r < 4; r++) o[nf][r] = 0.f;

    const unsigned lrow = (unsigned)(lane & 15);
    const unsigned lquad = (unsigned)((lane >> 4) * 16);
    const unsigned aqh = sb + S_QH + (w * 16 + lrow) * 272 + lquad;
    const unsigned aql = sb + S_QL + (w * 16 + lrow) * 272 + lquad;

    #pragma unroll 1
    for (int t = 0; t < 32; t++) {
        const int buf = t & 1;
        if (t < 31) { attn_issue_kv(sb, buf ^ 1, t + 1, tid, kh, kl, vth, vtl); CP_WAIT1(); }
        else        { CP_WAIT0(); }
        __syncthreads();

        const unsigned kb = sb + S_KV0 + buf * KVBUF;

        // ---- S = Q K^T (fused 3-pass split) ----
        float s[8][4];
        #pragma unroll
        for (int nf = 0; nf < 8; nf++)
            #pragma unroll
            for (int r = 0; r < 4; r++) s[nf][r] = 0.f;

        #pragma unroll
        for (int kc = 0; kc < 8; kc++) {
            unsigned ah[4], al[4];
            ldsm_x4(ah[0], ah[1], ah[2], ah[3], aqh + kc * 32);
            ldsm_x4(al[0], al[1], al[2], al[3], aql + kc * 32);
            #pragma unroll
            for (int bi = 0; bi < 4; bi++) {
                unsigned kbr = (unsigned)(bi * 16 + lrow) * 272 + lquad + kc * 32;
                unsigned bh4[4], bl4[4];
                ldsm_x4(bh4[0], bh4[1], bh4[2], bh4[3], kb + S_KH + kbr);
                ldsm_x4(bl4[0], bl4[1], bl4[2], bl4[3], kb + S_KL + kbr);
                mma16816(s[2*bi],   ah[0],ah[1],ah[2],ah[3], bh4[0], bh4[2]);
                mma16816(s[2*bi+1], ah[0],ah[1],ah[2],ah[3], bh4[1], bh4[3]);
                mma16816(s[2*bi],   ah[0],ah[1],ah[2],ah[3], bl4[0], bl4[2]);
                mma16816(s[2*bi+1], ah[0],ah[1],ah[2],ah[3], bl4[1], bl4[3]);
                mma16816(s[2*bi],   al[0],al[1],al[2],al[3], bh4[0], bh4[2]);
                mma16816(s[2*bi+1], al[0],al[1],al[2],al[3], bh4[1], bh4[3]);
            }
        }

        // ---- online softmax ----
        float mx0 = -1e30f, mx1 = -1e30f;
        #pragma unroll
        for (int nf = 0; nf < 8; nf++) {
            mx0 = fmaxf(mx0, fmaxf(s[nf][0], s[nf][1]));
            mx1 = fmaxf(mx1, fmaxf(s[nf][2], s[nf][3]));
        }
        mx0 = fmaxf(mx0, __shfl_xor_sync(0xffffffffu, mx0, 1));
        mx0 = fmaxf(mx0, __shfl_xor_sync(0xffffffffu, mx0, 2));
        mx1 = fmaxf(mx1, __shfl_xor_sync(0xffffffffu, mx1, 1));
        mx1 = fmaxf(mx1, __shfl_xor_sync(0xffffffffu, mx1, 2));
        float mn0 = fmaxf(m0, mx0), mn1 = fmaxf(m1, mx1);
        float c0 = __expf(m0 - mn0), c1 = __expf(m1 - mn1);
        m0 = mn0; m1 = mn1;
        float ls0 = 0.f, ls1 = 0.f;
        #pragma unroll
        for (int nf = 0; nf < 8; nf++) {
            s[nf][0] = __expf(s[nf][0] - mn0); ls0 += s[nf][0];
            s[nf][1] = __expf(s[nf][1] - mn0); ls0 += s[nf][1];
            s[nf][2] = __expf(s[nf][2] - mn1); ls1 += s[nf][2];
            s[nf][3] = __expf(s[nf][3] - mn1); ls1 += s[nf][3];
        }
        ls0 += __shfl_xor_sync(0xffffffffu, ls0, 1);
        ls0 += __shfl_xor_sync(0xffffffffu, ls0, 2);
        ls1 += __shfl_xor_sync(0xffffffffu, ls1, 1);
        ls1 += __shfl_xor_sync(0xffffffffu, ls1, 2);
        l0 = l0 * c0 + ls0;
        l1 = l1 * c1 + ls1;
        #pragma unroll
        for (int nf = 0; nf < 16; nf++) {
            o[nf][0] *= c0; o[nf][1] *= c0;
            o[nf][2] *= c1; o[nf][3] *= c1;
        }

        // ---- P -> bf16 split A-frags ----
        unsigned pah[4][4], pal[4][4];
        #pragma unroll
        for (int kc2 = 0; kc2 < 4; kc2++) {
            #pragma unroll
            for (int r = 0; r < 4; r++) {
                int nf = 2 * kc2 + (r >> 1);
                float v0 = s[nf][(r & 1) * 2], v1 = s[nf][(r & 1) * 2 + 1];
                split2(v0, v1, pah[kc2][r], pal[kc2][r]);
            }
        }

        // ---- O += P V (fused 3-pass split), V^T in smem [dim][key] ----
        #pragma unroll
        for (int kc2 = 0; kc2 < 4; kc2++) {
            #pragma unroll
            for (int nf2 = 0; nf2 < 8; nf2++) {
                unsigned vr = (unsigned)(nf2 * 16 + lrow) * 144 + lquad + kc2 * 32;
                unsigned vh4[4], vl4[4];
                ldsm_x4(vh4[0], vh4[1], vh4[2], vh4[3], kb + S_VH + vr);
                ldsm_x4(vl4[0], vl4[1], vl4[2], vl4[3], kb + S_VL + vr);
                mma16816(o[2*nf2],   pah[kc2][0],pah[kc2][1],pah[kc2][2],pah[kc2][3], vh4[0], vh4[2]);
                mma16816(o[2*nf2+1], pah[kc2][0],pah[kc2][1],pah[kc2][2],pah[kc2][3], vh4[1], vh4[3]);
                mma16816(o[2*nf2],   pah[kc2][0],pah[kc2][1],pah[kc2][2],pah[kc2][3], vl4[0], vl4[2]);
                mma16816(o[2*nf2+1], pah[kc2][0],pah[kc2][1],pah[kc2][2],pah[kc2][3], vl4[1], vl4[3]);
                mma16816(o[2*nf2],   pal[kc2][0],pal[kc2][1],pal[kc2][2],pal[kc2][3], vh4[0], vh4[2]);
                mma16816(o[2*nf2+1], pal[kc2][0],pal[kc2][1],pal[kc2][2],pal[kc2][3], vh4[1], vh4[3]);
            }
        }
        __syncthreads();
    }

    // ---- epilogue: normalize, split, store to ao [B,S,H] ----
    float il0 = 1.f / l0, il1 = 1.f / l1;
    const int b = bh >> 4, h = bh & 15;
    size_t srow = (size_t)q0 + w * 16 + (lane >> 2);
    size_t base0 = ((size_t)b * Ssz + srow) * Hsz + h * 128 + (lane & 3) * 2;
    size_t base1 = base0 + 8 * (size_t)Hsz;
    #pragma unroll
    for (int nf = 0; nf < 16; nf++) {
        unsigned hw, lw;
        split2(o[nf][0] * il0, o[nf][1] * il0, hw, lw);
        *(unsigned*)(AOh + base0 + nf * 8) = hw;
        *(unsigned*)(AOl + base0 + nf * 8) = lw;
        split2(o[nf][2] * il1, o[nf][3] * il1, hw, lw);
        *(unsigned*)(AOh + base1 + nf * 8) = hw;
        *(unsigned*)(AOl + base1 + nf * 8) = lw;
    }
}

// ---------------------------------------------------------------------------
extern "C" void kernel_launch(void* const* d_in, const int* in_sizes, int n_in,
                              void* d_out, int out_size)
{
    const float* x  = (const float*)d_in[0];
    const float* Wq = (const float*)d_in[1];
    const float* bq = (const float*)d_in[2];
    const float* Wk = (const float*)d_in[3];
    const float* bk = (const float*)d_in[4];
    const float* Wv = (const float*)d_in[5];
    const float* bv = (const float*)d_in[6];
    const float* Wo = (const float*)d_in[7];
    const float* bo = (const float*)d_in[8];
    float* out = (float*)d_out;

    __nv_bfloat16 *xhi, *xlo, *whi, *wlo, *qh, *ql, *kh, *kl, *vth, *vtl, *aoh, *aol;
    cudaGetSymbolAddress((void**)&xhi, g_xhi);
    cudaGetSymbolAddress((void**)&xlo, g_xlo);
    cudaGetSymbolAddress((void**)&whi, g_whi);
    cudaGetSymbolAddress((void**)&wlo, g_wlo);
    cudaGetSymbolAddress((void**)&qh,  g_qh);
    cudaGetSymbolAddress((void**)&ql,  g_ql);
    cudaGetSymbolAddress((void**)&kh,  g_kh);
    cudaGetSymbolAddress((void**)&kl,  g_kl);
    cudaGetSymbolAddress((void**)&vth, g_vth);
    cudaGetSymbolAddress((void**)&vtl, g_vtl);
    cudaGetSymbolAddress((void**)&aoh, g_aoh);
    cudaGetSymbolAddress((void**)&aol, g_aol);

    cudaFuncSetAttribute(gemm_mma<0>, cudaFuncAttributeMaxDynamicSharedMemorySize, GSMEM);
    cudaFuncSetAttribute(gemm_mma<1>, cudaFuncAttributeMaxDynamicSharedMemorySize, GSMEM);
    cudaFuncSetAttribute(gemm_mma<2>, cudaFuncAttributeMaxDynamicSharedMemorySize, GSMEM);
    cudaFuncSetAttribute(gemm_mma<3>, cudaFuncAttributeMaxDynamicSharedMemorySize, GSMEM);
    cudaFuncSetAttribute(attn_mma,    cudaFuncAttributeMaxDynamicSharedMemorySize, A_SMEM);

    dim3 tgrid(Hsz / 32, Hsz / 32, 4), tblk(32, 8);
    tsplit4_kernel<<<tgrid, tblk>>>(Wq, Wk, Wv, Wo, whi, wlo);
    split_kernel<<<2048, 256>>>(x, xhi, xlo, MK);

    dim3 ggrid(Hsz / 128, Msz / 128);   // (16, 64)
    gemm_mma<1><<<ggrid, 256, GSMEM>>>(xhi, xlo, whi + 0 * WK, wlo + 0 * WK, bq,
                                       nullptr, qh, ql);
    gemm_mma<2><<<ggrid, 256, GSMEM>>>(xhi, xlo, whi + 1 * WK, wlo + 1 * WK, bk,
                                       nullptr, kh, kl);
    gemm_mma<3><<<ggrid, 256, GSMEM>>>(xhi, xlo, whi + 2 * WK, wlo + 2 * WK, bv,
                                       nullptr, vth, vtl);

    dim3 agrid(Ssz / 128, Bsz * NH);    // (16, 64)
    attn_mma<<<agrid, 256, A_SMEM>>>(qh, ql, kh, kl, vth, vtl, aoh, aol);

    gemm_mma<0><<<ggrid, 256, GSMEM>>>(aoh, aol, whi + 3 * WK, wlo + 3 * WK, bo,
                                       out, nullptr, nullptr);
}

// round 7
// speedup vs baseline: 4.7105x; 1.0466x over previous
#include <cuda_runtime.h>
#include <cuda_bf16.h>
#include <math.h>

// Problem shape
#define Bsz 4
#define Ssz 2048
#define Hsz 2048
#define NH  16
#define HD  128
#define Msz (Bsz*Ssz)          // 8192
#define MK  ((size_t)Msz*Hsz)  // 16,777,216
#define WK  ((size_t)Hsz*Hsz)  // 4,194,304

#define QSCALE 0.08838834764831843f   // 1/sqrt(128)

// ---------------- scratch (__device__ globals; no cudaMalloc allowed) ------
__device__ __nv_bfloat16 g_xhi[MK], g_xlo[MK];
__device__ __nv_bfloat16 g_whi[4][WK], g_wlo[4][WK];   // W^T split, [N][K]
__device__ __nv_bfloat16 g_qh[MK], g_ql[MK];           // [B*nh][S][hd], scale folded
__device__ __nv_bfloat16 g_kh[MK], g_kl[MK];           // [B*nh][S][hd]
__device__ __nv_bfloat16 g_vth[MK], g_vtl[MK];         // V^T: [B*nh][hd][S]
__device__ __nv_bfloat16 g_aoh[MK], g_aol[MK];         // [B,S,H] split

// ---------------- PTX helpers ---------------------------------------------
__device__ __forceinline__ unsigned smem_u32(const void* p) {
    unsigned a;
    asm("{ .reg .u64 t; cvta.to.shared.u64 t, %1; cvt.u32.u64 %0, t; }"
        : "=r"(a) : "l"(p));
    return a;
}
__device__ __forceinline__ void ldsm_x4(unsigned& r0, unsigned& r1,
                                        unsigned& r2, unsigned& r3, unsigned a) {
    asm volatile("ldmatrix.sync.aligned.m8n8.x4.shared.b16 {%0,%1,%2,%3}, [%4];"
                 : "=r"(r0), "=r"(r1), "=r"(r2), "=r"(r3) : "r"(a));
}
__device__ __forceinline__ void mma16816(float* c, unsigned a0, unsigned a1,
                                         unsigned a2, unsigned a3,
                                         unsigned b0, unsigned b1) {
    asm volatile(
        "mma.sync.aligned.m16n8k16.row.col.f32.bf16.bf16.f32 "
        "{%0,%1,%2,%3}, {%4,%5,%6,%7}, {%8,%9}, {%0,%1,%2,%3};"
        : "+f"(c[0]), "+f"(c[1]), "+f"(c[2]), "+f"(c[3])
        : "r"(a0), "r"(a1), "r"(a2), "r"(a3), "r"(b0), "r"(b1));
}
__device__ __forceinline__ void cp16(unsigned dst, const void* src) {
    asm volatile("{ .reg .u64 g; cvta.to.global.u64 g, %1;\n\t"
                 "cp.async.cg.shared.global [%0], [g], 16; }"
                 :: "r"(dst), "l"(src) : "memory");
}
#define CP_COMMIT() asm volatile("cp.async.commit_group;" ::: "memory")
#define CP_WAIT1()  asm volatile("cp.async.wait_group 1;" ::: "memory")
#define CP_WAIT0()  asm volatile("cp.async.wait_group 0;" ::: "memory")

// split a float pair into hi/lo bf16x2 words
__device__ __forceinline__ void split2(float v0, float v1, unsigned& hi, unsigned& lo) {
    __nv_bfloat162 h = __float22bfloat162_rn(make_float2(v0, v1));
    hi = *(unsigned*)&h;
    float r0 = v0 - __bfloat162float(h.x);
    float r1 = v1 - __bfloat162float(h.y);
    __nv_bfloat162 l = __float22bfloat162_rn(make_float2(r0, r1));
    lo = *(unsigned*)&l;
}

// ---------------- conversion kernels --------------------------------------
__global__ void split_kernel(const float* __restrict__ in,
                             __nv_bfloat16* __restrict__ hi,
                             __nv_bfloat16* __restrict__ lo, size_t n) {
    for (size_t i = blockIdx.x * blockDim.x + threadIdx.x; i < n;
         i += (size_t)gridDim.x * blockDim.x) {
        float f = in[i];
        __nv_bfloat16 h = __float2bfloat16(f);
        hi[i] = h;
        lo[i] = __float2bfloat16(f - __bfloat162float(h));
    }
}

// All 4 weight transposes in one launch: W[K][N] -> Wt_hi/lo[N][K], z selects W
__global__ void tsplit4_kernel(const float* __restrict__ W0, const float* __restrict__ W1,
                               const float* __restrict__ W2, const float* __restrict__ W3,
                               __nv_bfloat16* __restrict__ hib,
                               __nv_bfloat16* __restrict__ lob) {
    __shared__ float tile[32][33];
    const float* W = (blockIdx.z == 0) ? W0 : (blockIdx.z == 1) ? W1
                     : (blockIdx.z == 2) ? W2 : W3;
    __nv_bfloat16* hi = hib + (size_t)blockIdx.z * WK;
    __nv_bfloat16* lo = lob + (size_t)blockIdx.z * WK;
    int bx = blockIdx.x * 32, by = blockIdx.y * 32;
    int tx = threadIdx.x, ty = threadIdx.y;
    #pragma unroll
    for (int i = 0; i < 32; i += 8)
        tile[ty + i][tx] = W[(size_t)(by + ty + i) * Hsz + bx + tx];
    __syncthreads();
    #pragma unroll
    for (int i = 0; i < 32; i += 8) {
        int n = bx + ty + i, k = by + tx;
        float f = tile[tx][ty + i];
        __nv_bfloat16 h = __float2bfloat16(f);
        hi[(size_t)n * Hsz + k] = h;
        lo[(size_t)n * Hsz + k] = __float2bfloat16(f - __bfloat162float(h));
    }
}

// ---------------- mma.sync split-bf16 GEMM ---------------------------------
// C[M,N] = A@B^T + bias. Block 128x128, K-chunk 64, 8 warps 2x4, warp 64x32.
// smem rows: 128 bf16 data + 8 pad = 144B pitch (odd multiple of 16 -> ldsm OK).
// MODE: 0 = fp32 out (Wo). 1 = Q split + QSCALE. 2 = K split. 3 = V^T split.
#define TPITCH 144
#define TILE_B (128*TPITCH)        // 18432
#define BUF_B  (4*TILE_B)          // 73728
#define GSMEM  (2*BUF_B)           // 147456

__device__ __forceinline__ void gemm_issue(const __nv_bfloat16* const* src,
                                           unsigned sb, int buf, int k0, int tid) {
    #pragma unroll
    for (int t = 0; t < 4; t++) {
        #pragma unroll
        for (int i = 0; i < 4; i++) {
            int idx = tid + i * 256;          // 0..1023
            int row = idx >> 3, ch = idx & 7;
            unsigned d = sb + buf * BUF_B + t * TILE_B + row * TPITCH + ch * 16;
            cp16(d, src[t] + (size_t)row * Hsz + k0 + ch * 8);
        }
    }
    CP_COMMIT();
}

template<int MODE>
__global__ void __launch_bounds__(256, 1) gemm_mma(
    const __nv_bfloat16* __restrict__ Ah, const __nv_bfloat16* __restrict__ Al,
    const __nv_bfloat16* __restrict__ Bh, const __nv_bfloat16* __restrict__ Bl,
    const float* __restrict__ bias, float* __restrict__ outf,
    __nv_bfloat16* __restrict__ oh, __nv_bfloat16* __restrict__ ol)
{
    extern __shared__ char smc[];
    const unsigned sb = smem_u32(smc);
    const int tid = threadIdx.x, wid = tid >> 5, lane = tid & 31;
    const int wm = wid >> 2, wn = wid & 3;
    const size_t bm = (size_t)blockIdx.y * 128, bn = (size_t)blockIdx.x * 128;

    const __nv_bfloat16* src[4] = { Ah + bm * Hsz, Al + bm * Hsz,
                                    Bh + bn * Hsz, Bl + bn * Hsz };

    float acc[4][4][4];
    #pragma unroll
    for (int mi = 0; mi < 4; mi++)
        #pragma unroll
        for (int ni = 0; ni < 4; ni++)
            #pragma unroll
            for (int r = 0; r < 4; r++) acc[mi][ni][r] = 0.f;

    const unsigned lm_off = (unsigned)((lane & 15) * TPITCH + (lane >> 4) * 16);

    gemm_issue(src, sb, 0, 0, tid);

    #pragma unroll 1
    for (int c = 0; c < 32; c++) {
        const int buf = c & 1;
        if (c < 31) { gemm_issue(src, sb, buf ^ 1, (c + 1) * 64, tid); CP_WAIT1(); }
        else        { CP_WAIT0(); }
        __syncthreads();

        const unsigned base   = sb + buf * BUF_B;
        const unsigned a_hi_b = base + (unsigned)(wm * 64 * TPITCH) + lm_off;
        const unsigned a_lo_b = a_hi_b + TILE_B;
        const unsigned b_hi_b = base + 2u * TILE_B + (unsigned)(wn * 32 * TPITCH) + lm_off;
        const unsigned b_lo_b = b_hi_b + TILE_B;

        #pragma unroll
        for (int ks = 0; ks < 4; ks++) {
            const unsigned ko = ks * 32;
            unsigned ah[4][4], al[4][4], bh[2][4], bl[2][4];
            // -- load hi frags, then hh MMAs (lo loads issue under MMA cover) --
            #pragma unroll
            for (int mi = 0; mi < 4; mi++)
                ldsm_x4(ah[mi][0], ah[mi][1], ah[mi][2], ah[mi][3],
                        a_hi_b + mi * 16 * TPITCH + ko);
            #pragma unroll
            for (int bi = 0; bi < 2; bi++)
                ldsm_x4(bh[bi][0], bh[bi][1], bh[bi][2], bh[bi][3],
                        b_hi_b + bi * 16 * TPITCH + ko);
            #pragma unroll
            for (int mi = 0; mi < 4; mi++)
                #pragma unroll
                for (int ni = 0; ni < 4; ni++)
                    mma16816(acc[mi][ni], ah[mi][0], ah[mi][1], ah[mi][2], ah[mi][3],
                             bh[ni >> 1][ni & 1], bh[ni >> 1][(ni & 1) + 2]);
            #pragma unroll
            for (int bi = 0; bi < 2; bi++)
                ldsm_x4(bl[bi][0], bl[bi][1], bl[bi][2], bl[bi][3],
                        b_lo_b + bi * 16 * TPITCH + ko);
            #pragma unroll
            for (int mi = 0; mi < 4; mi++)
                #pragma unroll
                for (int ni = 0; ni < 4; ni++)
                    mma16816(acc[mi][ni], ah[mi][0], ah[mi][1], ah[mi][2], ah[mi][3],
                             bl[ni >> 1][ni & 1], bl[ni >> 1][(ni & 1) + 2]);
            #pragma unroll
            for (int mi = 0; mi < 4; mi++)
                ldsm_x4(al[mi][0], al[mi][1], al[mi][2], al[mi][3],
                        a_lo_b + mi * 16 * TPITCH + ko);
            #pragma unroll
            for (int mi = 0; mi < 4; mi++)
                #pragma unroll
                for (int ni = 0; ni < 4; ni++)
                    mma16816(acc[mi][ni], al[mi][0], al[mi][1], al[mi][2], al[mi][3],
                             bh[ni >> 1][ni & 1], bh[ni >> 1][(ni & 1) + 2]);
        }
        __syncthreads();
    }

    const int r0 = lane >> 2;
    const int cc = (lane & 3) * 2;

    if (MODE == 3) {
        // stage tile as V^T [d][s] in smem, then coalesced 16B stores.
        unsigned short* sh = (unsigned short*)smc;          // 128 x 136 u16
        unsigned short* sl = sh + 128 * 136;
        #pragma unroll
        for (int mi = 0; mi < 4; mi++) {
            #pragma unroll
            for (int ni = 0; ni < 4; ni++) {
                int cl = wn * 32 + ni * 8 + cc;             // local d
                float2 bsv = *(const float2*)&bias[bn + cl];
                #pragma unroll
                for (int half = 0; half < 2; half++) {
                    int ml = wm * 64 + mi * 16 + r0 + half * 8;   // local s
                    float v0 = acc[mi][ni][half * 2 + 0] + bsv.x;
                    float v1 = acc[mi][ni][half * 2 + 1] + bsv.y;
                    unsigned hw, lw;
                    split2(v0, v1, hw, lw);
                    __nv_bfloat162 h2 = *(__nv_bfloat162*)&hw;
                    __nv_bfloat162 l2 = *(__nv_bfloat162*)&lw;
                    sh[(cl + 0) * 136 + ml] = *(unsigned short*)&h2.x;
                    sh[(cl + 1) * 136 + ml] = *(unsigned short*)&h2.y;
                    sl[(cl + 0) * 136 + ml] = *(unsigned short*)&l2.x;
                    sl[(cl + 1) * 136 + ml] = *(unsigned short*)&l2.y;
                }
            }
        }
        __syncthreads();
        const int hh = (int)(bn >> 7);
        const size_t b_ = bm >> 11, sbase = bm & 2047;
        const size_t rowbase = ((b_ * NH + hh) * (size_t)HD);
        #pragma unroll
        for (int i = 0; i < 8; i++) {
            int idx = tid + i * 256;        // 0..2047
            int d = idx >> 4, ch = idx & 15;
            uint4 vh = *(uint4*)(sh + d * 136 + ch * 8);
            uint4 vl = *(uint4*)(sl + d * 136 + ch * 8);
            size_t off = (rowbase + d) * Ssz + sbase + ch * 8;
            *(uint4*)(oh + off) = vh;
            *(uint4*)(ol + off) = vl;
        }
        return;
    }

    #pragma unroll
    for (int mi = 0; mi < 4; mi++) {
        #pragma unroll
        for (int ni = 0; ni < 4; ni++) {
            int col = (int)bn + wn * 32 + ni * 8 + cc;
            float2 bsv = *(const float2*)&bias[col];
            #pragma unroll
            for (int half = 0; half < 2; half++) {
                size_t m = bm + wm * 64 + mi * 16 + r0 + half * 8;
                float v0 = acc[mi][ni][half * 2 + 0] + bsv.x;
                float v1 = acc[mi][ni][half * 2 + 1] + bsv.y;
                if (MODE == 0) {
                    *(float2*)(outf + m * Hsz + col) = make_float2(v0, v1);
                } else {
                    if (MODE == 1) { v0 *= QSCALE; v1 *= QSCALE; }
                    unsigned hw, lw;
                    split2(v0, v1, hw, lw);
                    size_t b_ = m >> 11, s_ = m & 2047;
                    int hh = col >> 7, d = col & 127;
                    size_t idx = (((b_ * NH + hh) * Ssz) + s_) * HD + d;
                    *(unsigned*)(oh + idx) = hw;
                    *(unsigned*)(ol + idx) = lw;
                }
            }
        }
    }
}

// ---------------- attention: mma.sync bf16 split, FA2-style ----------------
// Block: 128 q-rows of one head, 8 warps x 16 rows. 64-key tiles, double-buffered.
// Q/K smem pitch 272B (136 bf16), V^T pitch 144B (72 bf16).
#define S_QH 0
#define S_QL 34816                 // 128*272
#define S_KV0 69632
#define S_KH 0
#define S_KL 17408                 // 64*272
#define S_VH 34816
#define S_VL 53248                 // +128*144
#define KVBUF 71680
#define A_SMEM (S_KV0 + 2*KVBUF)   // 212992

__device__ __forceinline__ void attn_issue_kv(
    unsigned sb, int buf, int t, int tid,
    const __nv_bfloat16* kh, const __nv_bfloat16* kl,
    const __nv_bfloat16* vth, const __nv_bfloat16* vtl)
{
    unsigned kb = sb + S_KV0 + buf * KVBUF;
    #pragma unroll
    for (int i = 0; i < 4; i++) {
        int idx = tid + i * 256; int row = idx >> 4, ch = idx & 15;
        cp16(kb + S_KH + row * 272 + ch * 16, kh + (size_t)(t * 64 + row) * HD + ch * 8);
        cp16(kb + S_KL + row * 272 + ch * 16, kl + (size_t)(t * 64 + row) * HD + ch * 8);
    }
    #pragma unroll
    for (int i = 0; i < 4; i++) {
        int idx = tid + i * 256; int row = idx >> 3, ch = idx & 7;
        cp16(kb + S_VH + row * 144 + ch * 16, vth + (size_t)row * Ssz + t * 64 + ch * 8);
        cp16(kb + S_VL + row * 144 + ch * 16, vtl + (size_t)row * Ssz + t * 64 + ch * 8);
    }
    CP_COMMIT();
}

__global__ void __launch_bounds__(256, 1) attn_mma(
    const __nv_bfloat16* __restrict__ Qhg, const __nv_bfloat16* __restrict__ Qlg,
    const __nv_bfloat16* __restrict__ Khg, const __nv_bfloat16* __restrict__ Klg,
    const __nv_bfloat16* __restrict__ Vthg, const __nv_bfloat16* __restrict__ Vtlg,
    __nv_bfloat16* __restrict__ AOh, __nv_bfloat16* __restrict__ AOl)
{
    extern __shared__ char smc[];
    const unsigned sb = smem_u32(smc);
    const int tid = threadIdx.x, w = tid >> 5, lane = tid & 31;
    const int bh = blockIdx.y, q0 = blockIdx.x * 128;

    const __nv_bfloat16* qh = Qhg + ((size_t)bh * Ssz + q0) * HD;
    const __nv_bfloat16* ql = Qlg + ((size_t)bh * Ssz + q0) * HD;
    const __nv_bfloat16* kh = Khg + (size_t)bh * Ssz * HD;
    const __nv_bfloat16* kl = Klg + (size_t)bh * Ssz * HD;
    const __nv_bfloat16* vth = Vthg + (size_t)bh * HD * Ssz;
    const __nv_bfloat16* vtl = Vtlg + (size_t)bh * HD * Ssz;

    #pragma unroll
    for (int i = 0; i < 8; i++) {
        int idx = tid + i * 256; int row = idx >> 4, ch = idx & 15;
        cp16(sb + S_QH + row * 272 + ch * 16, qh + (size_t)row * HD + ch * 8);
        cp16(sb + S_QL + row * 272 + ch * 16, ql + (size_t)row * HD + ch * 8);
    }
    attn_issue_kv(sb, 0, 0, tid, kh, kl, vth, vtl);

    float m0 = -1e30f, m1 = -1e30f, l0 = 0.f, l1 = 0.f;
    float o[16][4];
    #pragma unroll
    for (int nf = 0; nf < 16; nf++)
        #pragma unroll
        for (int r = 0; r < 4; r++) o[nf][r] = 0.f;

    const unsigned lrow = (unsigned)(lane & 15);
    const unsigned lquad = (unsigned)((lane >> 4) * 16);
    const unsigned aqh = sb + S_QH + (w * 16 + lrow) * 272 + lquad;
    const unsigned aql = sb + S_QL + (w * 16 + lrow) * 272 + lquad;

    #pragma unroll 1
    for (int t = 0; t < 32; t++) {
        const int buf = t & 1;
        if (t < 31) { attn_issue_kv(sb, buf ^ 1, t + 1, tid, kh, kl, vth, vtl); CP_WAIT1(); }
        else        { CP_WAIT0(); }
        __syncthreads();

        const unsigned kb = sb + S_KV0 + buf * KVBUF;

        // ---- S = Q K^T (fused 3-pass split; all frags loaded up front) ----
        float s[8][4];
        #pragma unroll
        for (int nf = 0; nf < 8; nf++)
            #pragma unroll
            for (int r = 0; r < 4; r++) s[nf][r] = 0.f;

        #pragma unroll
        for (int kc = 0; kc < 8; kc++) {
            unsigned ah[4], al[4], bh4[4][4], bl4[4][4];
            ldsm_x4(ah[0], ah[1], ah[2], ah[3], aqh + kc * 32);
            ldsm_x4(al[0], al[1], al[2], al[3], aql + kc * 32);
            #pragma unroll
            for (int bi = 0; bi < 4; bi++) {
                unsigned kbr = (unsigned)(bi * 16 + lrow) * 272 + lquad + kc * 32;
                ldsm_x4(bh4[bi][0], bh4[bi][1], bh4[bi][2], bh4[bi][3], kb + S_KH + kbr);
                ldsm_x4(bl4[bi][0], bl4[bi][1], bl4[bi][2], bl4[bi][3], kb + S_KL + kbr);
            }
            #pragma unroll
            for (int bi = 0; bi < 4; bi++) {
                mma16816(s[2*bi],   ah[0],ah[1],ah[2],ah[3], bh4[bi][0], bh4[bi][2]);
                mma16816(s[2*bi+1], ah[0],ah[1],ah[2],ah[3], bh4[bi][1], bh4[bi][3]);
            }
            #pragma unroll
            for (int bi = 0; bi < 4; bi++) {
                mma16816(s[2*bi],   ah[0],ah[1],ah[2],ah[3], bl4[bi][0], bl4[bi][2]);
                mma16816(s[2*bi+1], ah[0],ah[1],ah[2],ah[3], bl4[bi][1], bl4[bi][3]);
            }
            #pragma unroll
            for (int bi = 0; bi < 4; bi++) {
                mma16816(s[2*bi],   al[0],al[1],al[2],al[3], bh4[bi][0], bh4[bi][2]);
                mma16816(s[2*bi+1], al[0],al[1],al[2],al[3], bh4[bi][1], bh4[bi][3]);
            }
        }

        // ---- online softmax ----
        float mx0 = -1e30f, mx1 = -1e30f;
        #pragma unroll
        for (int nf = 0; nf < 8; nf++) {
            mx0 = fmaxf(mx0, fmaxf(s[nf][0], s[nf][1]));
            mx1 = fmaxf(mx1, fmaxf(s[nf][2], s[nf][3]));
        }
        mx0 = fmaxf(mx0, __shfl_xor_sync(0xffffffffu, mx0, 1));
        mx0 = fmaxf(mx0, __shfl_xor_sync(0xffffffffu, mx0, 2));
        mx1 = fmaxf(mx1, __shfl_xor_sync(0xffffffffu, mx1, 1));
        mx1 = fmaxf(mx1, __shfl_xor_sync(0xffffffffu, mx1, 2));
        float mn0 = fmaxf(m0, mx0), mn1 = fmaxf(m1, mx1);
        float c0 = __expf(m0 - mn0), c1 = __expf(m1 - mn1);
        m0 = mn0; m1 = mn1;
        float ls0 = 0.f, ls1 = 0.f;
        #pragma unroll
        for (int nf = 0; nf < 8; nf++) {
            s[nf][0] = __expf(s[nf][0] - mn0); ls0 += s[nf][0];
            s[nf][1] = __expf(s[nf][1] - mn0); ls0 += s[nf][1];
            s[nf][2] = __expf(s[nf][2] - mn1); ls1 += s[nf][2];
            s[nf][3] = __expf(s[nf][3] - mn1); ls1 += s[nf][3];
        }
        ls0 += __shfl_xor_sync(0xffffffffu, ls0, 1);
        ls0 += __shfl_xor_sync(0xffffffffu, ls0, 2);
        ls1 += __shfl_xor_sync(0xffffffffu, ls1, 1);
        ls1 += __shfl_xor_sync(0xffffffffu, ls1, 2);
        l0 = l0 * c0 + ls0;
        l1 = l1 * c1 + ls1;
        #pragma unroll
        for (int nf = 0; nf < 16; nf++) {
            o[nf][0] *= c0; o[nf][1] *= c0;
            o[nf][2] *= c1; o[nf][3] *= c1;
        }

        // ---- P -> bf16 split A-frags ----
        unsigned pah[4][4], pal[4][4];
        #pragma unroll
        for (int kc2 = 0; kc2 < 4; kc2++) {
            #pragma unroll
            for (int r = 0; r < 4; r++) {
                int nf = 2 * kc2 + (r >> 1);
                float v0 = s[nf][(r & 1) * 2], v1 = s[nf][(r & 1) * 2 + 1];
                split2(v0, v1, pah[kc2][r], pal[kc2][r]);
            }
        }

        // ---- O += P V (fused 3-pass), V-frags double-buffered ----
        #pragma unroll
        for (int kc2 = 0; kc2 < 4; kc2++) {
            unsigned vh4[2][4], vl4[2][4];
            {
                unsigned vr = lrow * 144 + lquad + kc2 * 32;
                ldsm_x4(vh4[0][0], vh4[0][1], vh4[0][2], vh4[0][3], kb + S_VH + vr);
                ldsm_x4(vl4[0][0], vl4[0][1], vl4[0][2], vl4[0][3], kb + S_VL + vr);
            }
            #pragma unroll
            for (int nf2 = 0; nf2 < 8; nf2++) {
                const int cur = nf2 & 1, nxt = cur ^ 1;
                if (nf2 < 7) {
                    unsigned vr = (unsigned)((nf2 + 1) * 16 + lrow) * 144 + lquad + kc2 * 32;
                    ldsm_x4(vh4[nxt][0], vh4[nxt][1], vh4[nxt][2], vh4[nxt][3], kb + S_VH + vr);
                    ldsm_x4(vl4[nxt][0], vl4[nxt][1], vl4[nxt][2], vl4[nxt][3], kb + S_VL + vr);
                }
                mma16816(o[2*nf2],   pah[kc2][0],pah[kc2][1],pah[kc2][2],pah[kc2][3], vh4[cur][0], vh4[cur][2]);
                mma16816(o[2*nf2+1], pah[kc2][0],pah[kc2][1],pah[kc2][2],pah[kc2][3], vh4[cur][1], vh4[cur][3]);
                mma16816(o[2*nf2],   pah[kc2][0],pah[kc2][1],pah[kc2][2],pah[kc2][3], vl4[cur][0], vl4[cur][2]);
                mma16816(o[2*nf2+1], pah[kc2][0],pah[kc2][1],pah[kc2][2],pah[kc2][3], vl4[cur][1], vl4[cur][3]);
                mma16816(o[2*nf2],   pal[kc2][0],pal[kc2][1],pal[kc2][2],pal[kc2][3], vh4[cur][0], vh4[cur][2]);
                mma16816(o[2*nf2+1], pal[kc2][0],pal[kc2][1],pal[kc2][2],pal[kc2][3], vh4[cur][1], vh4[cur][3]);
            }
        }
        __syncthreads();
    }

    // ---- epilogue: normalize, split, store to ao [B,S,H] ----
    float il0 = 1.f / l0, il1 = 1.f / l1;
    const int b = bh >> 4, h = bh & 15;
    size_t srow = (size_t)q0 + w * 16 + (lane >> 2);
    size_t base0 = ((size_t)b * Ssz + srow) * Hsz + h * 128 + (lane & 3) * 2;
    size_t base1 = base0 + 8 * (size_t)Hsz;
    #pragma unroll
    for (int nf = 0; nf < 16; nf++) {
        unsigned hw, lw;
        split2(o[nf][0] * il0, o[nf][1] * il0, hw, lw);
        *(unsigned*)(AOh + base0 + nf * 8) = hw;
        *(unsigned*)(AOl + base0 + nf * 8) = lw;
        split2(o[nf][2] * il1, o[nf][3] * il1, hw, lw);
        *(unsigned*)(AOh + base1 + nf * 8) = hw;
        *(unsigned*)(AOl + base1 + nf * 8) = lw;
    }
}

// ---------------------------------------------------------------------------
extern "C" void kernel_launch(void* const* d_in, const int* in_sizes, int n_in,
                              void* d_out, int out_size)
{
    const float* x  = (const float*)d_in[0];
    const float* Wq = (const float*)d_in[1];
    const float* bq = (const float*)d_in[2];
    const float* Wk = (const float*)d_in[3];
    const float* bk = (const float*)d_in[4];
    const float* Wv = (const float*)d_in[5];
    const float* bv = (const float*)d_in[6];
    const float* Wo = (const float*)d_in[7];
    const float* bo = (const float*)d_in[8];
    float* out = (float*)d_out;

    __nv_bfloat16 *xhi, *xlo, *whi, *wlo, *qh, *ql, *kh, *kl, *vth, *vtl, *aoh, *aol;
    cudaGetSymbolAddress((void**)&xhi, g_xhi);
    cudaGetSymbolAddress((void**)&xlo, g_xlo);
    cudaGetSymbolAddress((void**)&whi, g_whi);
    cudaGetSymbolAddress((void**)&wlo, g_wlo);
    cudaGetSymbolAddress((void**)&qh,  g_qh);
    cudaGetSymbolAddress((void**)&ql,  g_ql);
    cudaGetSymbolAddress((void**)&kh,  g_kh);
    cudaGetSymbolAddress((void**)&kl,  g_kl);
    cudaGetSymbolAddress((void**)&vth, g_vth);
    cudaGetSymbolAddress((void**)&vtl, g_vtl);
    cudaGetSymbolAddress((void**)&aoh, g_aoh);
    cudaGetSymbolAddress((void**)&aol, g_aol);

    cudaFuncSetAttribute(gemm_mma<0>, cudaFuncAttributeMaxDynamicSharedMemorySize, GSMEM);
    cudaFuncSetAttribute(gemm_mma<1>, cudaFuncAttributeMaxDynamicSharedMemorySize, GSMEM);
    cudaFuncSetAttribute(gemm_mma<2>, cudaFuncAttributeMaxDynamicSharedMemorySize, GSMEM);
    cudaFuncSetAttribute(gemm_mma<3>, cudaFuncAttributeMaxDynamicSharedMemorySize, GSMEM);
    cudaFuncSetAttribute(attn_mma,    cudaFuncAttributeMaxDynamicSharedMemorySize, A_SMEM);

    dim3 tgrid(Hsz / 32, Hsz / 32, 4), tblk(32, 8);
    tsplit4_kernel<<<tgrid, tblk>>>(Wq, Wk, Wv, Wo, whi, wlo);
    split_kernel<<<2048, 256>>>(x, xhi, xlo, MK);

    dim3 ggrid(Hsz / 128, Msz / 128);   // (16, 64)
    gemm_mma<1><<<ggrid, 256, GSMEM>>>(xhi, xlo, whi + 0 * WK, wlo + 0 * WK, bq,
                                       nullptr, qh, ql);
    gemm_mma<2><<<ggrid, 256, GSMEM>>>(xhi, xlo, whi + 1 * WK, wlo + 1 * WK, bk,
                                       nullptr, kh, kl);
    gemm_mma<3><<<ggrid, 256, GSMEM>>>(xhi, xlo, whi + 2 * WK, wlo + 2 * WK, bv,
                                       nullptr, vth, vtl);

    dim3 agrid(Ssz / 128, Bsz * NH);    // (16, 64)
    attn_mma<<<agrid, 256, A_SMEM>>>(qh, ql, kh, kl, vth, vtl, aoh, aol);

    gemm_mma<0><<<ggrid, 256, GSMEM>>>(aoh, aol, whi + 3 * WK, wlo + 3 * WK, bo,
                                       out, nullptr, nullptr);
}

// round 8
// speedup vs baseline: 4.7669x; 1.0120x over previous
#include <cuda_runtime.h>
#include <cuda_bf16.h>
#include <math.h>

// Problem shape
#define Bsz 4
#define Ssz 2048
#define Hsz 2048
#define NH  16
#define HD  128
#define Msz (Bsz*Ssz)          // 8192
#define MK  ((size_t)Msz*Hsz)  // 16,777,216
#define WK  ((size_t)Hsz*Hsz)  // 4,194,304

#define QSCALE 0.08838834764831843f   // 1/sqrt(128)

// ---------------- scratch (__device__ globals; no cudaMalloc allowed) ------
__device__ __nv_bfloat16 g_xhi[MK], g_xlo[MK];
__device__ __nv_bfloat16 g_whi[4][WK], g_wlo[4][WK];   // W^T split, [N][K]
__device__ __nv_bfloat16 g_qh[MK], g_ql[MK];           // [B*nh][S][hd], scale folded
__device__ __nv_bfloat16 g_kh[MK], g_kl[MK];           // [B*nh][S][hd]
__device__ __nv_bfloat16 g_vth[MK], g_vtl[MK];         // V^T: [B*nh][hd][S]
__device__ __nv_bfloat16 g_aoh[MK], g_aol[MK];         // [B,S,H] split

// ---------------- PTX helpers ---------------------------------------------
__device__ __forceinline__ unsigned smem_u32(const void* p) {
    unsigned a;
    asm("{ .reg .u64 t; cvta.to.shared.u64 t, %1; cvt.u32.u64 %0, t; }"
        : "=r"(a) : "l"(p));
    return a;
}
__device__ __forceinline__ void ldsm_x4(unsigned& r0, unsigned& r1,
                                        unsigned& r2, unsigned& r3, unsigned a) {
    asm volatile("ldmatrix.sync.aligned.m8n8.x4.shared.b16 {%0,%1,%2,%3}, [%4];"
                 : "=r"(r0), "=r"(r1), "=r"(r2), "=r"(r3) : "r"(a));
}
__device__ __forceinline__ void mma16816(float* c, unsigned a0, unsigned a1,
                                         unsigned a2, unsigned a3,
                                         unsigned b0, unsigned b1) {
    asm volatile(
        "mma.sync.aligned.m16n8k16.row.col.f32.bf16.bf16.f32 "
        "{%0,%1,%2,%3}, {%4,%5,%6,%7}, {%8,%9}, {%0,%1,%2,%3};"
        : "+f"(c[0]), "+f"(c[1]), "+f"(c[2]), "+f"(c[3])
        : "r"(a0), "r"(a1), "r"(a2), "r"(a3), "r"(b0), "r"(b1));
}
__device__ __forceinline__ void cp16(unsigned dst, const void* src) {
    asm volatile("{ .reg .u64 g; cvta.to.global.u64 g, %1;\n\t"
                 "cp.async.cg.shared.global [%0], [g], 16; }"
                 :: "r"(dst), "l"(src) : "memory");
}
#define CP_COMMIT() asm volatile("cp.async.commit_group;" ::: "memory")
#define CP_WAIT1()  asm volatile("cp.async.wait_group 1;" ::: "memory")
#define CP_WAIT0()  asm volatile("cp.async.wait_group 0;" ::: "memory")

// split a float pair into hi/lo bf16x2 words
__device__ __forceinline__ void split2(float v0, float v1, unsigned& hi, unsigned& lo) {
    __nv_bfloat162 h = __float22bfloat162_rn(make_float2(v0, v1));
    hi = *(unsigned*)&h;
    float r0 = v0 - __bfloat162float(h.x);
    float r1 = v1 - __bfloat162float(h.y);
    __nv_bfloat162 l = __float22bfloat162_rn(make_float2(r0, r1));
    lo = *(unsigned*)&l;
}

// ---------------- conversion kernels --------------------------------------
__global__ void split_kernel(const float* __restrict__ in,
                             __nv_bfloat16* __restrict__ hi,
                             __nv_bfloat16* __restrict__ lo, size_t n) {
    for (size_t i = blockIdx.x * blockDim.x + threadIdx.x; i < n;
         i += (size_t)gridDim.x * blockDim.x) {
        float f = in[i];
        __nv_bfloat16 h = __float2bfloat16(f);
        hi[i] = h;
        lo[i] = __float2bfloat16(f - __bfloat162float(h));
    }
}

// All 4 weight transposes in one launch: W[K][N] -> Wt_hi/lo[N][K], z selects W
__global__ void tsplit4_kernel(const float* __restrict__ W0, const float* __restrict__ W1,
                               const float* __restrict__ W2, const float* __restrict__ W3,
                               __nv_bfloat16* __restrict__ hib,
                               __nv_bfloat16* __restrict__ lob) {
    __shared__ float tile[32][33];
    const float* W = (blockIdx.z == 0) ? W0 : (blockIdx.z == 1) ? W1
                     : (blockIdx.z == 2) ? W2 : W3;
    __nv_bfloat16* hi = hib + (size_t)blockIdx.z * WK;
    __nv_bfloat16* lo = lob + (size_t)blockIdx.z * WK;
    int bx = blockIdx.x * 32, by = blockIdx.y * 32;
    int tx = threadIdx.x, ty = threadIdx.y;
    #pragma unroll
    for (int i = 0; i < 32; i += 8)
        tile[ty + i][tx] = W[(size_t)(by + ty + i) * Hsz + bx + tx];
    __syncthreads();
    #pragma unroll
    for (int i = 0; i < 32; i += 8) {
        int n = bx + ty + i, k = by + tx;
        float f = tile[tx][ty + i];
        __nv_bfloat16 h = __float2bfloat16(f);
        hi[(size_t)n * Hsz + k] = h;
        lo[(size_t)n * Hsz + k] = __float2bfloat16(f - __bfloat162float(h));
    }
}

// ---------------- mma.sync split-bf16 GEMM (512 thr, 16 warps 4x4) ---------
// C[M,N] = A@B^T + bias. Block 128x128, K-chunk 64, warp tile 32x32.
#define TPITCH 144
#define TILE_B (128*TPITCH)        // 18432
#define BUF_B  (4*TILE_B)          // 73728
#define GSMEM  (2*BUF_B)           // 147456

__device__ __forceinline__ void gemm_issue512(const __nv_bfloat16* const* src,
                                              unsigned sb, int buf, int k0, int tid) {
    #pragma unroll
    for (int t = 0; t < 4; t++) {
        #pragma unroll
        for (int i = 0; i < 2; i++) {
            int idx = tid + i * 512;          // 0..1023
            int row = idx >> 3, ch = idx & 7;
            unsigned d = sb + buf * BUF_B + t * TILE_B + row * TPITCH + ch * 16;
            cp16(d, src[t] + (size_t)row * Hsz + k0 + ch * 8);
        }
    }
    CP_COMMIT();
}

// core mainloop: fills acc[2][4][4] for warp tile (wm*32, wn*32)
__device__ __forceinline__ void gemm_core512(
    const __nv_bfloat16* Ah, const __nv_bfloat16* Al,
    const __nv_bfloat16* Bh, const __nv_bfloat16* Bl,
    unsigned sb, int tid, int wm, int wn, int lane, float acc[2][4][4])
{
    const __nv_bfloat16* src[4] = { Ah, Al, Bh, Bl };
    const unsigned lm_off = (unsigned)((lane & 15) * TPITCH + (lane >> 4) * 16);

    gemm_issue512(src, sb, 0, 0, tid);

    #pragma unroll 1
    for (int c = 0; c < 32; c++) {
        const int buf = c & 1;
        if (c < 31) { gemm_issue512(src, sb, buf ^ 1, (c + 1) * 64, tid); CP_WAIT1(); }
        else        { CP_WAIT0(); }
        __syncthreads();

        const unsigned base   = sb + buf * BUF_B;
        const unsigned a_hi_b = base + (unsigned)(wm * 32 * TPITCH) + lm_off;
        const unsigned a_lo_b = a_hi_b + TILE_B;
        const unsigned b_hi_b = base + 2u * TILE_B + (unsigned)(wn * 32 * TPITCH) + lm_off;
        const unsigned b_lo_b = b_hi_b + TILE_B;

        #pragma unroll
        for (int ks = 0; ks < 4; ks++) {
            const unsigned ko = ks * 32;
            unsigned ah[2][4], al[2][4], bh[2][4], bl[2][4];
            #pragma unroll
            for (int mi = 0; mi < 2; mi++)
                ldsm_x4(ah[mi][0], ah[mi][1], ah[mi][2], ah[mi][3],
                        a_hi_b + mi * 16 * TPITCH + ko);
            #pragma unroll
            for (int bi = 0; bi < 2; bi++)
                ldsm_x4(bh[bi][0], bh[bi][1], bh[bi][2], bh[bi][3],
                        b_hi_b + bi * 16 * TPITCH + ko);
            #pragma unroll
            for (int mi = 0; mi < 2; mi++)
                #pragma unroll
                for (int ni = 0; ni < 4; ni++)
                    mma16816(acc[mi][ni], ah[mi][0], ah[mi][1], ah[mi][2], ah[mi][3],
                             bh[ni >> 1][ni & 1], bh[ni >> 1][(ni & 1) + 2]);
            #pragma unroll
            for (int bi = 0; bi < 2; bi++)
                ldsm_x4(bl[bi][0], bl[bi][1], bl[bi][2], bl[bi][3],
                        b_lo_b + bi * 16 * TPITCH + ko);
            #pragma unroll
            for (int mi = 0; mi < 2; mi++)
                #pragma unroll
                for (int ni = 0; ni < 4; ni++)
                    mma16816(acc[mi][ni], ah[mi][0], ah[mi][1], ah[mi][2], ah[mi][3],
                             bl[ni >> 1][ni & 1], bl[ni >> 1][(ni & 1) + 2]);
            #pragma unroll
            for (int mi = 0; mi < 2; mi++)
                ldsm_x4(al[mi][0], al[mi][1], al[mi][2], al[mi][3],
                        a_lo_b + mi * 16 * TPITCH + ko);
            #pragma unroll
            for (int mi = 0; mi < 2; mi++)
                #pragma unroll
                for (int ni = 0; ni < 4; ni++)
                    mma16816(acc[mi][ni], al[mi][0], al[mi][1], al[mi][2], al[mi][3],
                             bh[ni >> 1][ni & 1], bh[ni >> 1][(ni & 1) + 2]);
        }
        __syncthreads();
    }
}

// Fused Q/K/V projection: blockIdx.z = 0(Q) 1(K) 2(V^T)
__global__ void __launch_bounds__(512, 1) gemm_qkv(
    const __nv_bfloat16* __restrict__ Ah, const __nv_bfloat16* __restrict__ Al,
    const __nv_bfloat16* __restrict__ Whi, const __nv_bfloat16* __restrict__ Wlo,
    const float* __restrict__ bq, const float* __restrict__ bk,
    const float* __restrict__ bv,
    __nv_bfloat16* __restrict__ qh, __nv_bfloat16* __restrict__ ql,
    __nv_bfloat16* __restrict__ kh, __nv_bfloat16* __restrict__ kl,
    __nv_bfloat16* __restrict__ vth, __nv_bfloat16* __restrict__ vtl)
{
    extern __shared__ char smc[];
    const unsigned sb = smem_u32(smc);
    const int tid = threadIdx.x, wid = tid >> 5, lane = tid & 31;
    const int wm = wid >> 2, wn = wid & 3;
    const int z = blockIdx.z;
    const size_t bm = (size_t)blockIdx.y * 128, bn = (size_t)blockIdx.x * 128;

    const __nv_bfloat16* Bh = Whi + (size_t)z * WK + bn * Hsz;
    const __nv_bfloat16* Bl = Wlo + (size_t)z * WK + bn * Hsz;
    const float* bias = (z == 0) ? bq : (z == 1) ? bk : bv;

    float acc[2][4][4];
    #pragma unroll
    for (int mi = 0; mi < 2; mi++)
        #pragma unroll
        for (int ni = 0; ni < 4; ni++)
            #pragma unroll
            for (int r = 0; r < 4; r++) acc[mi][ni][r] = 0.f;

    gemm_core512(Ah + bm * Hsz, Al + bm * Hsz, Bh, Bl, sb, tid, wm, wn, lane, acc);

    const int r0 = lane >> 2;
    const int cc = (lane & 3) * 2;

    if (z == 2) {
        // stage tile as V^T [d][s] in smem, then coalesced 16B stores.
        unsigned short* sh = (unsigned short*)smc;          // 128 x 136 u16
        unsigned short* sl = sh + 128 * 136;
        #pragma unroll
        for (int mi = 0; mi < 2; mi++) {
            #pragma unroll
            for (int ni = 0; ni < 4; ni++) {
                int cl = wn * 32 + ni * 8 + cc;             // local d
                float2 bsv = *(const float2*)&bias[bn + cl];
                #pragma unroll
                for (int half = 0; half < 2; half++) {
                    int ml = wm * 32 + mi * 16 + r0 + half * 8;   // local s
                    float v0 = acc[mi][ni][half * 2 + 0] + bsv.x;
                    float v1 = acc[mi][ni][half * 2 + 1] + bsv.y;
                    unsigned hw, lw;
                    split2(v0, v1, hw, lw);
                    __nv_bfloat162 h2 = *(__nv_bfloat162*)&hw;
                    __nv_bfloat162 l2 = *(__nv_bfloat162*)&lw;
                    sh[(cl + 0) * 136 + ml] = *(unsigned short*)&h2.x;
                    sh[(cl + 1) * 136 + ml] = *(unsigned short*)&h2.y;
                    sl[(cl + 0) * 136 + ml] = *(unsigned short*)&l2.x;
                    sl[(cl + 1) * 136 + ml] = *(unsigned short*)&l2.y;
                }
            }
        }
        __syncthreads();
        const int hh = (int)(bn >> 7);
        const size_t b_ = bm >> 11, sbase = bm & 2047;
        const size_t rowbase = ((b_ * NH + hh) * (size_t)HD);
        #pragma unroll
        for (int i = 0; i < 4; i++) {
            int idx = tid + i * 512;        // 0..2047
            int d = idx >> 4, ch = idx & 15;
            uint4 vh = *(uint4*)(sh + d * 136 + ch * 8);
            uint4 vl = *(uint4*)(sl + d * 136 + ch * 8);
            size_t off = (rowbase + d) * Ssz + sbase + ch * 8;
            *(uint4*)(vth + off) = vh;
            *(uint4*)(vtl + off) = vl;
        }
        return;
    }

    __nv_bfloat16* oh = (z == 0) ? qh : kh;
    __nv_bfloat16* ol = (z == 0) ? ql : kl;
    const float scale = (z == 0) ? QSCALE : 1.f;
    #pragma unroll
    for (int mi = 0; mi < 2; mi++) {
        #pragma unroll
        for (int ni = 0; ni < 4; ni++) {
            int col = (int)bn + wn * 32 + ni * 8 + cc;
            float2 bsv = *(const float2*)&bias[col];
            #pragma unroll
            for (int half = 0; half < 2; half++) {
                size_t m = bm + wm * 32 + mi * 16 + r0 + half * 8;
                float v0 = (acc[mi][ni][half * 2 + 0] + bsv.x) * scale;
                float v1 = (acc[mi][ni][half * 2 + 1] + bsv.y) * scale;
                unsigned hw, lw;
                split2(v0, v1, hw, lw);
                size_t b_ = m >> 11, s_ = m & 2047;
                int hh = col >> 7, d = col & 127;
                size_t idx = (((b_ * NH + hh) * Ssz) + s_) * HD + d;
                *(unsigned*)(oh + idx) = hw;
                *(unsigned*)(ol + idx) = lw;
            }
        }
    }
}

// Output projection: fp32 result
__global__ void __launch_bounds__(512, 1) gemm_out(
    const __nv_bfloat16* __restrict__ Ah, const __nv_bfloat16* __restrict__ Al,
    const __nv_bfloat16* __restrict__ Bh, const __nv_bfloat16* __restrict__ Bl,
    const float* __restrict__ bias, float* __restrict__ outf)
{
    extern __shared__ char smc[];
    const unsigned sb = smem_u32(smc);
    const int tid = threadIdx.x, wid = tid >> 5, lane = tid & 31;
    const int wm = wid >> 2, wn = wid & 3;
    const size_t bm = (size_t)blockIdx.y * 128, bn = (size_t)blockIdx.x * 128;

    float acc[2][4][4];
    #pragma unroll
    for (int mi = 0; mi < 2; mi++)
        #pragma unroll
        for (int ni = 0; ni < 4; ni++)
            #pragma unroll
            for (int r = 0; r < 4; r++) acc[mi][ni][r] = 0.f;

    gemm_core512(Ah + bm * Hsz, Al + bm * Hsz, Bh + bn * Hsz, Bl + bn * Hsz,
                 sb, tid, wm, wn, lane, acc);

    const int r0 = lane >> 2;
    const int cc = (lane & 3) * 2;
    #pragma unroll
    for (int mi = 0; mi < 2; mi++) {
        #pragma unroll
        for (int ni = 0; ni < 4; ni++) {
            int col = (int)bn + wn * 32 + ni * 8 + cc;
            float2 bsv = *(const float2*)&bias[col];
            #pragma unroll
            for (int half = 0; half < 2; half++) {
                size_t m = bm + wm * 32 + mi * 16 + r0 + half * 8;
                *(float2*)(outf + m * Hsz + col) =
                    make_float2(acc[mi][ni][half * 2 + 0] + bsv.x,
                                acc[mi][ni][half * 2 + 1] + bsv.y);
            }
        }
    }
}

// ---------------- attention: mma.sync bf16 split, FA2-style ----------------
// Block: 128 q-rows of one head, 8 warps x 16 rows. 64-key tiles, double-buffered.
#define S_QH 0
#define S_QL 34816                 // 128*272
#define S_KV0 69632
#define S_KH 0
#define S_KL 17408                 // 64*272
#define S_VH 34816
#define S_VL 53248                 // +128*144
#define KVBUF 71680
#define A_SMEM (S_KV0 + 2*KVBUF)   // 212992

__device__ __forceinline__ void attn_issue_kv(
    unsigned sb, int buf, int t, int tid,
    const __nv_bfloat16* kh, const __nv_bfloat16* kl,
    const __nv_bfloat16* vth, const __nv_bfloat16* vtl)
{
    unsigned kb = sb + S_KV0 + buf * KVBUF;
    #pragma unroll
    for (int i = 0; i < 4; i++) {
        int idx = tid + i * 256; int row = idx >> 4, ch = idx & 15;
        cp16(kb + S_KH + row * 272 + ch * 16, kh + (size_t)(t * 64 + row) * HD + ch * 8);
        cp16(kb + S_KL + row * 272 + ch * 16, kl + (size_t)(t * 64 + row) * HD + ch * 8);
    }
    #pragma unroll
    for (int i = 0; i < 4; i++) {
        int idx = tid + i * 256; int row = idx >> 3, ch = idx & 7;
        cp16(kb + S_VH + row * 144 + ch * 16, vth + (size_t)row * Ssz + t * 64 + ch * 8);
        cp16(kb + S_VL + row * 144 + ch * 16, vtl + (size_t)row * Ssz + t * 64 + ch * 8);
    }
    CP_COMMIT();
}

__global__ void __launch_bounds__(256, 1) attn_mma(
    const __nv_bfloat16* __restrict__ Qhg, const __nv_bfloat16* __restrict__ Qlg,
    const __nv_bfloat16* __restrict__ Khg, const __nv_bfloat16* __restrict__ Klg,
    const __nv_bfloat16* __restrict__ Vthg, const __nv_bfloat16* __restrict__ Vtlg,
    __nv_bfloat16* __restrict__ AOh, __nv_bfloat16* __restrict__ AOl)
{
    extern __shared__ char smc[];
    const unsigned sb = smem_u32(smc);
    const int tid = threadIdx.x, w = tid >> 5, lane = tid & 31;
    const int bh = blockIdx.y, q0 = blockIdx.x * 128;

    const __nv_bfloat16* qh = Qhg + ((size_t)bh * Ssz + q0) * HD;
    const __nv_bfloat16* ql = Qlg + ((size_t)bh * Ssz + q0) * HD;
    const __nv_bfloat16* kh = Khg + (size_t)bh * Ssz * HD;
    const __nv_bfloat16* kl = Klg + (size_t)bh * Ssz * HD;
    const __nv_bfloat16* vth = Vthg + (size_t)bh * HD * Ssz;
    const __nv_bfloat16* vtl = Vtlg + (size_t)bh * HD * Ssz;

    #pragma unroll
    for (int i = 0; i < 8; i++) {
        int idx = tid + i * 256; int row = idx >> 4, ch = idx & 15;
        cp16(sb + S_QH + row * 272 + ch * 16, qh + (size_t)row * HD + ch * 8);
        cp16(sb + S_QL + row * 272 + ch * 16, ql + (size_t)row * HD + ch * 8);
    }
    attn_issue_kv(sb, 0, 0, tid, kh, kl, vth, vtl);

    float m0 = -1e30f, m1 = -1e30f, l0 = 0.f, l1 = 0.f;
    float o[16][4];
    #pragma unroll
    for (int nf = 0; nf < 16; nf++)
        #pragma unroll
        for (int r = 0; r < 4; r++) o[nf][r] = 0.f;

    const unsigned lrow = (unsigned)(lane & 15);
    const unsigned lquad = (unsigned)((lane >> 4) * 16);
    const unsigned aqh = sb + S_QH + (w * 16 + lrow) * 272 + lquad;
    const unsigned aql = sb + S_QL + (w * 16 + lrow) * 272 + lquad;

    #pragma unroll 1
    for (int t = 0; t < 32; t++) {
        const int buf = t & 1;
        if (t < 31) { attn_issue_kv(sb, buf ^ 1, t + 1, tid, kh, kl, vth, vtl); CP_WAIT1(); }
        else        { CP_WAIT0(); }
        __syncthreads();

        const unsigned kb = sb + S_KV0 + buf * KVBUF;

        float s[8][4];
        #pragma unroll
        for (int nf = 0; nf < 8; nf++)
            #pragma unroll
            for (int r = 0; r < 4; r++) s[nf][r] = 0.f;

        #pragma unroll
        for (int kc = 0; kc < 8; kc++) {
            unsigned ah[4], al[4], bh4[4][4], bl4[4][4];
            ldsm_x4(ah[0], ah[1], ah[2], ah[3], aqh + kc * 32);
            ldsm_x4(al[0], al[1], al[2], al[3], aql + kc * 32);
            #pragma unroll
            for (int bi = 0; bi < 4; bi++) {
                unsigned kbr = (unsigned)(bi * 16 + lrow) * 272 + lquad + kc * 32;
                ldsm_x4(bh4[bi][0], bh4[bi][1], bh4[bi][2], bh4[bi][3], kb + S_KH + kbr);
                ldsm_x4(bl4[bi][0], bl4[bi][1], bl4[bi][2], bl4[bi][3], kb + S_KL + kbr);
            }
            #pragma unroll
            for (int bi = 0; bi < 4; bi++) {
                mma16816(s[2*bi],   ah[0],ah[1],ah[2],ah[3], bh4[bi][0], bh4[bi][2]);
                mma16816(s[2*bi+1], ah[0],ah[1],ah[2],ah[3], bh4[bi][1], bh4[bi][3]);
            }
            #pragma unroll
            for (int bi = 0; bi < 4; bi++) {
                mma16816(s[2*bi],   ah[0],ah[1],ah[2],ah[3], bl4[bi][0], bl4[bi][2]);
                mma16816(s[2*bi+1], ah[0],ah[1],ah[2],ah[3], bl4[bi][1], bl4[bi][3]);
            }
            #pragma unroll
            for (int bi = 0; bi < 4; bi++) {
                mma16816(s[2*bi],   al[0],al[1],al[2],al[3], bh4[bi][0], bh4[bi][2]);
                mma16816(s[2*bi+1], al[0],al[1],al[2],al[3], bh4[bi][1], bh4[bi][3]);
            }
        }

        // ---- online softmax ----
        float mx0 = -1e30f, mx1 = -1e30f;
        #pragma unroll
        for (int nf = 0; nf < 8; nf++) {
            mx0 = fmaxf(mx0, fmaxf(s[nf][0], s[nf][1]));
            mx1 = fmaxf(mx1, fmaxf(s[nf][2], s[nf][3]));
        }
        mx0 = fmaxf(mx0, __shfl_xor_sync(0xffffffffu, mx0, 1));
        mx0 = fmaxf(mx0, __shfl_xor_sync(0xffffffffu, mx0, 2));
        mx1 = fmaxf(mx1, __shfl_xor_sync(0xffffffffu, mx1, 1));
        mx1 = fmaxf(mx1, __shfl_xor_sync(0xffffffffu, mx1, 2));
        float mn0 = fmaxf(m0, mx0), mn1 = fmaxf(m1, mx1);
        float c0 = __expf(m0 - mn0), c1 = __expf(m1 - mn1);
        m0 = mn0; m1 = mn1;
        float ls0 = 0.f, ls1 = 0.f;
        #pragma unroll
        for (int nf = 0; nf < 8; nf++) {
            s[nf][0] = __expf(s[nf][0] - mn0); ls0 += s[nf][0];
            s[nf][1] = __expf(s[nf][1] - mn0); ls0 += s[nf][1];
            s[nf][2] = __expf(s[nf][2] - mn1); ls1 += s[nf][2];
            s[nf][3] = __expf(s[nf][3] - mn1); ls1 += s[nf][3];
        }
        ls0 += __shfl_xor_sync(0xffffffffu, ls0, 1);
        ls0 += __shfl_xor_sync(0xffffffffu, ls0, 2);
        ls1 += __shfl_xor_sync(0xffffffffu, ls1, 1);
        ls1 += __shfl_xor_sync(0xffffffffu, ls1, 2);
        l0 = l0 * c0 + ls0;
        l1 = l1 * c1 + ls1;
        #pragma unroll
        for (int nf = 0; nf < 16; nf++) {
            o[nf][0] *= c0; o[nf][1] *= c0;
            o[nf][2] *= c1; o[nf][3] *= c1;
        }

        // ---- P -> bf16 split A-frags ----
        unsigned pah[4][4], pal[4][4];
        #pragma unroll
        for (int kc2 = 0; kc2 < 4; kc2++) {
            #pragma unroll
            for (int r = 0; r < 4; r++) {
                int nf = 2 * kc2 + (r >> 1);
                float v0 = s[nf][(r & 1) * 2], v1 = s[nf][(r & 1) * 2 + 1];
                split2(v0, v1, pah[kc2][r], pal[kc2][r]);
            }
        }

        // ---- O += P V (fused 3-pass), V-frags double-buffered ----
        #pragma unroll
        for (int kc2 = 0; kc2 < 4; kc2++) {
            unsigned vh4[2][4], vl4[2][4];
            {
                unsigned vr = lrow * 144 + lquad + kc2 * 32;
                ldsm_x4(vh4[0][0], vh4[0][1], vh4[0][2], vh4[0][3], kb + S_VH + vr);
                ldsm_x4(vl4[0][0], vl4[0][1], vl4[0][2], vl4[0][3], kb + S_VL + vr);
            }
            #pragma unroll
            for (int nf2 = 0; nf2 < 8; nf2++) {
                const int cur = nf2 & 1, nxt = cur ^ 1;
                if (nf2 < 7) {
                    unsigned vr = (unsigned)((nf2 + 1) * 16 + lrow) * 144 + lquad + kc2 * 32;
                    ldsm_x4(vh4[nxt][0], vh4[nxt][1], vh4[nxt][2], vh4[nxt][3], kb + S_VH + vr);
                    ldsm_x4(vl4[nxt][0], vl4[nxt][1], vl4[nxt][2], vl4[nxt][3], kb + S_VL + vr);
                }
                mma16816(o[2*nf2],   pah[kc2][0],pah[kc2][1],pah[kc2][2],pah[kc2][3], vh4[cur][0], vh4[cur][2]);
                mma16816(o[2*nf2+1], pah[kc2][0],pah[kc2][1],pah[kc2][2],pah[kc2][3], vh4[cur][1], vh4[cur][3]);
                mma16816(o[2*nf2],   pah[kc2][0],pah[kc2][1],pah[kc2][2],pah[kc2][3], vl4[cur][0], vl4[cur][2]);
                mma16816(o[2*nf2+1], pah[kc2][0],pah[kc2][1],pah[kc2][2],pah[kc2][3], vl4[cur][1], vl4[cur][3]);
                mma16816(o[2*nf2],   pal[kc2][0],pal[kc2][1],pal[kc2][2],pal[kc2][3], vh4[cur][0], vh4[cur][2]);
                mma16816(o[2*nf2+1], pal[kc2][0],pal[kc2][1],pal[kc2][2],pal[kc2][3], vh4[cur][1], vh4[cur][3]);
            }
        }
        __syncthreads();
    }

    // ---- epilogue: normalize, split, store to ao [B,S,H] ----
    float il0 = 1.f / l0, il1 = 1.f / l1;
    const int b = bh >> 4, h = bh & 15;
    size_t srow = (size_t)q0 + w * 16 + (lane >> 2);
    size_t base0 = ((size_t)b * Ssz + srow) * Hsz + h * 128 + (lane & 3) * 2;
    size_t base1 = base0 + 8 * (size_t)Hsz;
    #pragma unroll
    for (int nf = 0; nf < 16; nf++) {
        unsigned hw, lw;
        split2(o[nf][0] * il0, o[nf][1] * il0, hw, lw);
        *(unsigned*)(AOh + base0 + nf * 8) = hw;
        *(unsigned*)(AOl + base0 + nf * 8) = lw;
        split2(o[nf][2] * il1, o[nf][3] * il1, hw, lw);
        *(unsigned*)(AOh + base1 + nf * 8) = hw;
        *(unsigned*)(AOl + base1 + nf * 8) = lw;
    }
}

// ---------------------------------------------------------------------------
extern "C" void kernel_launch(void* const* d_in, const int* in_sizes, int n_in,
                              void* d_out, int out_size)
{
    const float* x  = (const float*)d_in[0];
    const float* Wq = (const float*)d_in[1];
    const float* bq = (const float*)d_in[2];
    const float* Wk = (const float*)d_in[3];
    const float* bk = (const float*)d_in[4];
    const float* Wv = (const float*)d_in[5];
    const float* bv = (const float*)d_in[6];
    const float* Wo = (const float*)d_in[7];
    const float* bo = (const float*)d_in[8];
    float* out = (float*)d_out;

    __nv_bfloat16 *xhi, *xlo, *whi, *wlo, *qh, *ql, *kh, *kl, *vth, *vtl, *aoh, *aol;
    cudaGetSymbolAddress((void**)&xhi, g_xhi);
    cudaGetSymbolAddress((void**)&xlo, g_xlo);
    cudaGetSymbolAddress((void**)&whi, g_whi);
    cudaGetSymbolAddress((void**)&wlo, g_wlo);
    cudaGetSymbolAddress((void**)&qh,  g_qh);
    cudaGetSymbolAddress((void**)&ql,  g_ql);
    cudaGetSymbolAddress((void**)&kh,  g_kh);
    cudaGetSymbolAddress((void**)&kl,  g_kl);
    cudaGetSymbolAddress((void**)&vth, g_vth);
    cudaGetSymbolAddress((void**)&vtl, g_vtl);
    cudaGetSymbolAddress((void**)&aoh, g_aoh);
    cudaGetSymbolAddress((void**)&aol, g_aol);

    cudaFuncSetAttribute(gemm_qkv, cudaFuncAttributeMaxDynamicSharedMemorySize, GSMEM);
    cudaFuncSetAttribute(gemm_out, cudaFuncAttributeMaxDynamicSharedMemorySize, GSMEM);
    cudaFuncSetAttribute(attn_mma, cudaFuncAttributeMaxDynamicSharedMemorySize, A_SMEM);

    dim3 tgrid(Hsz / 32, Hsz / 32, 4), tblk(32, 8);
    tsplit4_kernel<<<tgrid, tblk>>>(Wq, Wk, Wv, Wo, whi, wlo);
    split_kernel<<<2048, 256>>>(x, xhi, xlo, MK);

    dim3 qkvgrid(Hsz / 128, Msz / 128, 3);   // (16, 64, 3)
    gemm_qkv<<<qkvgrid, 512, GSMEM>>>(xhi, xlo, whi, wlo, bq, bk, bv,
                                      qh, ql, kh, kl, vth, vtl);

    dim3 agrid(Ssz / 128, Bsz * NH);         // (16, 64)
    attn_mma<<<agrid, 256, A_SMEM>>>(qh, ql, kh, kl, vth, vtl, aoh, aol);

    dim3 ogrid(Hsz / 128, Msz / 128);        // (16, 64)
    gemm_out<<<ogrid, 512, GSMEM>>>(aoh, aol, whi + 3 * WK, wlo + 3 * WK, bo, out);
}